// round 10
// baseline (speedup 1.0000x reference)
#include <cuda_runtime.h>
#include <cuda_fp16.h>
#include <cstdint>

#define D      256
#define K      2048
#define BHW    4096
#define NPIX   65536
#define QELEMS 16777216
#define MARGIN 0.25f

// ---------------- device scratch ----------------
// A scratch (hi only): [b*32+pt][px 128][c 32 (^= px&7)] uint4 (c = 8 halves of d)
__device__ uint4 g_xA[(size_t)512 * 128 * 32];          // 32 MB
// B scratch (hi only): [step 32][n 256][cl 8 (^= n&7)] uint4
__device__ uint4 g_xB[(size_t)32 * 256 * 8];            // 1 MB
__device__ float g_halfnorm[K];
__device__ int   g_idx[NPIX];
__device__ int   g_counts[K];
__device__ float g_loss;
__device__ int   g_ambig_cnt;
__device__ int   g_ambig[NPIX];

__device__ __forceinline__ void mma16(float* c, const uint32_t* a, const uint32_t* b) {
    asm volatile("mma.sync.aligned.m16n8k16.row.col.f32.f16.f16.f32 "
        "{%0,%1,%2,%3}, {%4,%5,%6,%7}, {%8,%9}, {%0,%1,%2,%3};"
        : "+f"(c[0]), "+f"(c[1]), "+f"(c[2]), "+f"(c[3])
        : "r"(a[0]), "r"(a[1]), "r"(a[2]), "r"(a[3]), "r"(b[0]), "r"(b[1]));
}
__device__ __forceinline__ void ldsm4(uint32_t* r, uint32_t addr) {
    asm volatile("ldmatrix.sync.aligned.m8n8.x4.shared.b16 {%0,%1,%2,%3}, [%4];"
        : "=r"(r[0]), "=r"(r[1]), "=r"(r[2]), "=r"(r[3]) : "r"(addr));
}
__device__ __forceinline__ uint32_t smem_u32(const void* p) {
    uint32_t a;
    asm("{ .reg .u64 t; cvta.to.shared.u64 t, %1; cvt.u32.u64 %0, t; }" : "=r"(a) : "l"(p));
    return a;
}
#define CPASYNC(dst, src) \
    asm volatile("cp.async.ca.shared.global [%0], [%1], 16;" :: "r"(dst), "l"(src))
#define CPCOMMIT() asm volatile("cp.async.commit_group;" ::: "memory")
#define CPWAIT0()  asm volatile("cp.async.wait_group 0;" ::: "memory")

__device__ __forceinline__ uint32_t packh2(float a, float b) {
    __half2 h2 = __halves2half2(__float2half_rn(a), __float2half_rn(b));
    return *reinterpret_cast<uint32_t*>(&h2);
}

// ---------------- kernel 0: halfnorm + zero counters ----------------
__global__ void prep_kernel(const float* __restrict__ emb) {
    int k = blockIdx.x * blockDim.x + threadIdx.x;
    if (k < K) {
        const float4* row = reinterpret_cast<const float4*>(emb + (size_t)k * D);
        float s = 0.f;
        #pragma unroll
        for (int i = 0; i < D / 4; i++) {
            float4 v = row[i];
            s += v.x * v.x + v.y * v.y + v.z * v.z + v.w * v.w;
        }
        g_halfnorm[k] = 0.5f * s;
        g_counts[k] = 0;
        if (k == 0) { g_loss = 0.f; g_ambig_cnt = 0; }
    }
}

// ---------------- kernel 1: -x -> fp16 hi, ldmatrix-ready A scratch ----------------
// grid: (b 16) x (pt 32) x (hpx 2) = 1024 blocks, 256 threads
__global__ void split_x_kernel(const float* __restrict__ x) {
    __shared__ uint4 stg[64 * 32];   // [pxl][cs]
    int blk = blockIdx.x;
    int b = blk >> 6, pt = (blk >> 1) & 31, hpx = blk & 1;
    int tid = threadIdx.x;
    int hw0 = pt * 128 + hpx * 64;

    #pragma unroll
    for (int it = 0; it < 8; it++) {
        int id = tid + it * 256;
        int pxl = id & 63, c = id >> 6;
        float v[8];
        #pragma unroll
        for (int j = 0; j < 8; j++)
            v[j] = -x[((size_t)(b * 256 + c * 8 + j)) * 4096 + hw0 + pxl];
        uint4 hi;
        hi.x = packh2(v[0], v[1]); hi.y = packh2(v[2], v[3]);
        hi.z = packh2(v[4], v[5]); hi.w = packh2(v[6], v[7]);
        stg[pxl * 32 + (c ^ (pxl & 7))] = hi;
    }
    __syncthreads();
    size_t ob = (size_t)(blk >> 1) * 4096;
    #pragma unroll
    for (int it = 0; it < 8; it++) {
        int id = tid + it * 256;
        int pxl = id >> 5, cp = id & 31;
        g_xA[ob + (size_t)(hpx * 64 + pxl) * 32 + cp] = stg[pxl * 32 + cp];
    }
}

// ---------------- kernel 2: e -> fp16 hi, ldmatrix-ready B scratch ----------------
// grid: 32 blocks (64 n each), 256 threads
__global__ void split_e_kernel(const float* __restrict__ emb) {
    __shared__ uint4 stg[64 * 32];   // [nl][cs]
    int n0 = blockIdx.x * 64;
    int tid = threadIdx.x;
    #pragma unroll
    for (int it = 0; it < 8; it++) {
        int id = tid + it * 256;
        int c = id & 31, nl = id >> 5;
        float v[8];
        #pragma unroll
        for (int j = 0; j < 8; j++)
            v[j] = emb[(size_t)(n0 + nl) * D + c * 8 + j];
        uint4 hi;
        hi.x = packh2(v[0], v[1]); hi.y = packh2(v[2], v[3]);
        hi.z = packh2(v[4], v[5]); hi.w = packh2(v[6], v[7]);
        int s = c >> 3, cl = c & 7;
        stg[nl * 32 + s * 8 + (cl ^ (nl & 7))] = hi;
    }
    __syncthreads();
    int nt = n0 >> 8;
    #pragma unroll
    for (int it = 0; it < 8; it++) {
        int id = tid + it * 256;        // [s 4][nl 64][clp 8]
        int clp = id & 7, nl = (id >> 3) & 63, s = id >> 9;
        g_xB[((size_t)(nt * 4 + s) * 256 + (n0 & 255) + nl) * 8 + clp] =
            stg[nl * 32 + s * 8 + clp];
    }
}

// ---------------- kernel 3: fp16-hi screening GEMM + top2 argmin ----------------
// smem: A[128][32]u4 = 64KB | B[2buf][256][8]u4 = 64KB | srv/sr2/sri 6KB
#define BOFF   65536
#define SRVW   32768
#define SR2W   33280
#define SRIW   33792
#define SMEM_BYTES 137216

__global__ __launch_bounds__(512, 1) void argmin_fp16_kernel() {
    extern __shared__ uint4 sm4[];
    uint32_t sb = smem_u32(sm4);
    uint32_t* smw = reinterpret_cast<uint32_t*>(sm4);
    float* srv = reinterpret_cast<float*>(smw + SRVW);
    float* sr2 = reinterpret_cast<float*>(smw + SR2W);
    int*   sri = reinterpret_cast<int*>(smw + SRIW);

    int tid = threadIdx.x;
    int w = tid >> 5, lane = tid & 31;
    int warpM = w >> 2, warpN = w & 3;        // 4 x 4 warps; tile 32px x 64n
    int g = lane >> 2, tig = lane & 3;

    srv[tid] = 3.4e38f; sr2[tid] = 3.4e38f; sri[tid] = 0;

    // prologue: A resident (8/thread) + B step0 (4/thread)
    {
        const uint4* asrc = &g_xA[(size_t)blockIdx.x * 4096];
        #pragma unroll
        for (int i = 0; i < 8; i++) {
            int id = tid + i * 512;
            CPASYNC(sb + id * 16, asrc + id);
        }
        #pragma unroll
        for (int i = 0; i < 4; i++) {
            int id = tid + i * 512;
            CPASYNC(sb + BOFF + id * 16, &g_xB[id]);
        }
        CPCOMMIT();
        CPWAIT0();
    }

    int pxA0 = warpM * 32 + (lane & 15);
    int kcA  = lane >> 4;
    int nB0  = warpN * 64 + (lane & 7) + ((lane >> 4) << 3);
    int kcB  = (lane >> 3) & 1;

    float acc[2][8][4];

    for (int nt = 0; nt < 8; nt++) {
        #pragma unroll
        for (int mf = 0; mf < 2; mf++)
            #pragma unroll
            for (int nf = 0; nf < 8; nf++)
                #pragma unroll
                for (int i = 0; i < 4; i++) acc[mf][nf][i] = 0.f;

        for (int s = 0; s < 4; s++) {
            int step = nt * 4 + s;
            int buf = step & 1;
            __syncthreads();
            if (step < 31) {
                const uint4* bsrc = &g_xB[(size_t)(step + 1) * 2048];
                uint32_t bdst = sb + BOFF + (buf ^ 1) * 32768;
                #pragma unroll
                for (int i = 0; i < 4; i++) {
                    int id = tid + i * 512;
                    CPASYNC(bdst + id * 16, bsrc + id);
                }
                CPCOMMIT();
            }
            uint32_t bbase = sb + BOFF + buf * 32768;
            #pragma unroll
            for (int kb = 0; kb < 4; kb++) {
                int cA = s * 8 + kb * 2 + kcA;
                uint32_t ah[2][4];
                #pragma unroll
                for (int mf = 0; mf < 2; mf++) {
                    int px = pxA0 + mf * 16;
                    uint32_t ro = (uint32_t)(px * 32 + (cA ^ (px & 7))) * 16;
                    ldsm4(ah[mf], sb + ro);
                }
                int clB = kb * 2 + kcB;
                uint32_t bh[4][4];
                #pragma unroll
                for (int p = 0; p < 4; p++) {
                    int n = nB0 + p * 16;
                    uint32_t ro = (uint32_t)(n * 8 + (clB ^ (n & 7))) * 16;
                    ldsm4(bh[p], bbase + ro);
                }
                #pragma unroll
                for (int mf = 0; mf < 2; mf++)
                    #pragma unroll
                    for (int nf = 0; nf < 8; nf++)
                        mma16(acc[mf][nf], ah[mf], &bh[nf >> 1][(nf & 1) * 2]);
            }
            CPWAIT0();
        }
        // epilogue: add halfnorm, per-pixel top-2 fold
        float hn[8][2];
        int colbase = nt * 256 + warpN * 64 + tig * 2;
        #pragma unroll
        for (int nf = 0; nf < 8; nf++) {
            hn[nf][0] = __ldg(&g_halfnorm[colbase + nf * 8]);
            hn[nf][1] = __ldg(&g_halfnorm[colbase + nf * 8 + 1]);
        }
        #pragma unroll
        for (int mf = 0; mf < 2; mf++) {
            #pragma unroll
            for (int half = 0; half < 2; half++) {
                float v = 3.4e38f, v2 = 3.4e38f; int vi = 0;
                #pragma unroll
                for (int nf = 0; nf < 8; nf++) {
                    #pragma unroll
                    for (int c = 0; c < 2; c++) {
                        float sc = acc[mf][nf][half * 2 + c] + hn[nf][c];
                        int ci = colbase + nf * 8 + c;
                        if (sc < v) { v2 = v; v = sc; vi = ci; }
                        else if (sc < v2) { v2 = sc; }
                    }
                }
                #pragma unroll
                for (int o = 1; o <= 2; o <<= 1) {
                    float ov  = __shfl_xor_sync(0xffffffffu, v, o);
                    int   oi  = __shfl_xor_sync(0xffffffffu, vi, o);
                    float ov2 = __shfl_xor_sync(0xffffffffu, v2, o);
                    float nv2 = fminf(fmaxf(v, ov), fminf(v2, ov2));
                    bool take = (ov < v) || (ov == v && oi < vi);
                    if (take) { v = ov; vi = oi; }
                    v2 = nv2;
                }
                if (tig == 0) {
                    int row = warpM * 32 + mf * 16 + half * 8 + g;
                    int slot = row * 4 + warpN;
                    float sv = srv[slot], sv2 = sr2[slot]; int si = sri[slot];
                    float nv2 = fminf(fmaxf(v, sv), fminf(v2, sv2));
                    bool take = (v < sv) || (v == sv && vi < si);
                    srv[slot] = take ? v : sv;
                    sri[slot] = take ? vi : si;
                    sr2[slot] = nv2;
                }
            }
        }
    }
    __syncthreads();
    if (tid < 128) {
        float v = srv[tid * 4], v2 = sr2[tid * 4]; int vi = sri[tid * 4];
        #pragma unroll
        for (int ww = 1; ww < 4; ww++) {
            float ov = srv[tid * 4 + ww], ov2 = sr2[tid * 4 + ww];
            int oi = sri[tid * 4 + ww];
            float nv2 = fminf(fmaxf(v, ov), fminf(v2, ov2));
            bool take = (ov < v) || (ov == v && oi < vi);
            if (take) { v = ov; vi = oi; }
            v2 = nv2;
        }
        int n = blockIdx.x * 128 + tid;
        g_idx[n] = vi;
        if (v2 - v < MARGIN) {
            int pos = atomicAdd(&g_ambig_cnt, 1);
            g_ambig[pos] = n;
        }
    }
}

// ---------------- kernel 4: exact fp32 brute force for ambiguous pixels ----------------
#define BR_PX 8
__global__ __launch_bounds__(256, 4) void brute_kernel(const float* __restrict__ x,
                                                       const float* __restrict__ emb) {
    __shared__ float sx[BR_PX][256];
    __shared__ float bv[BR_PX * 256];
    __shared__ int   bi[BR_PX * 256];
    int tid = threadIdx.x, lane = tid & 31;
    int count = g_ambig_cnt;
    const float4* emb4 = reinterpret_cast<const float4*>(emb);

    for (int batch = blockIdx.x; batch * BR_PX < count; batch += gridDim.x) {
        __syncthreads();
        for (int i = tid; i < BR_PX * 256; i += 256) {
            int px = i >> 8, d = i & 255;
            int li = batch * BR_PX + px;
            if (li >= count) li = count - 1;
            int n = g_ambig[li];
            sx[px][d] = x[(((size_t)(n >> 12) * 256 + d) << 12) | (size_t)(n & 4095)];
        }
        __syncthreads();

        float v[BR_PX]; int vi[BR_PX];
        #pragma unroll
        for (int p = 0; p < BR_PX; p++) { v[p] = 3.4e38f; vi[p] = 0; }
        for (int kk = 0; kk < 8; kk++) {
            int k = kk * 256 + tid;
            float dot[BR_PX];
            #pragma unroll
            for (int p = 0; p < BR_PX; p++) dot[p] = 0.f;
            const float4* er = emb4 + (size_t)k * 64;
            for (int c = 0; c < 64; c++) {
                float4 e4 = er[c];
                #pragma unroll
                for (int p = 0; p < BR_PX; p++) {
                    dot[p] = fmaf(sx[p][c * 4],     e4.x, dot[p]);
                    dot[p] = fmaf(sx[p][c * 4 + 1], e4.y, dot[p]);
                    dot[p] = fmaf(sx[p][c * 4 + 2], e4.z, dot[p]);
                    dot[p] = fmaf(sx[p][c * 4 + 3], e4.w, dot[p]);
                }
            }
            float hn = g_halfnorm[k];
            #pragma unroll
            for (int p = 0; p < BR_PX; p++) {
                float sc = hn - dot[p];
                if (sc < v[p]) { v[p] = sc; vi[p] = k; }
            }
        }
        #pragma unroll
        for (int p = 0; p < BR_PX; p++) { bv[p * 256 + tid] = v[p]; bi[p * 256 + tid] = vi[p]; }
        __syncthreads();
        // warp p reduces pixel p
        int px = tid >> 5;
        float rv = 3.4e38f; int ri = 0;
        for (int j = 0; j < 8; j++) {
            int idx = px * 256 + lane + j * 32;
            float ov = bv[idx]; int oi = bi[idx];
            if (ov < rv || (ov == rv && oi < ri)) { rv = ov; ri = oi; }
        }
        #pragma unroll
        for (int o = 16; o >= 1; o >>= 1) {
            float ov = __shfl_xor_sync(0xffffffffu, rv, o);
            int   oi = __shfl_xor_sync(0xffffffffu, ri, o);
            if (ov < rv || (ov == rv && oi < ri)) { rv = ov; ri = oi; }
        }
        if (lane == 0) {
            int li = batch * BR_PX + px;
            if (li < count) g_idx[g_ambig[li]] = ri;
        }
    }
}

// ---------------- kernel 5: gather quantized + loss partials ----------------
__global__ void quantize_kernel(const float* __restrict__ x,
                                const float* __restrict__ emb,
                                float* __restrict__ outq) {
    int o = blockIdx.x * 256 + threadIdx.x;
    int hw = o & (BHW - 1);
    int d  = (o >> 12) & (D - 1);
    int b  = o >> 20;
    int n  = (b << 12) | hw;
    int k  = g_idx[n];
    float q  = __ldg(emb + (size_t)k * D + d);
    float xv = x[o];
    __stcs(outq + o, q);
    float diff = q - xv;
    float l = diff * diff;
    #pragma unroll
    for (int off = 16; off; off >>= 1) l += __shfl_xor_sync(0xffffffffu, l, off);
    __shared__ float ls[8];
    int lane = threadIdx.x & 31, w = threadIdx.x >> 5;
    if (lane == 0) ls[w] = l;
    __syncthreads();
    if (threadIdx.x == 0) {
        float ssum = 0.f;
        #pragma unroll
        for (int i = 0; i < 8; i++) ssum += ls[i];
        atomicAdd(&g_loss, ssum);
    }
}

// ---------------- kernel 6: histogram ----------------
__global__ void hist_kernel() {
    int n = blockIdx.x * 256 + threadIdx.x;
    atomicAdd(&g_counts[g_idx[n]], 1);
}

// ---------------- kernel 7: one-hot encodings ----------------
__global__ void enc_kernel(float2* __restrict__ enc) {
    int i2 = blockIdx.x * 256 + threadIdx.x;
    int n = i2 >> 10;
    int j = (i2 & 1023) << 1;
    int k = g_idx[n];
    float2 v;
    v.x = (j == k)     ? 1.f : 0.f;
    v.y = (j + 1 == k) ? 1.f : 0.f;
    __stcs(enc + i2, v);
}

// ---------------- kernel 8: scalars ----------------
__global__ void final_kernel(float* __restrict__ out) {
    __shared__ float sh[256];
    int t = threadIdx.x;
    float s = 0.f;
    for (int k = t; k < K; k += 256) {
        float p = (float)g_counts[k] * (1.0f / (float)NPIX);
        s += p * logf(p + 1e-10f);
    }
    sh[t] = s;
    __syncthreads();
    for (int o = 128; o; o >>= 1) {
        if (t < o) sh[t] += sh[t + o];
        __syncthreads();
    }
    if (t == 0) {
        out[0] = 0.25f * g_loss / (float)QELEMS;
        out[1 + QELEMS] = expf(-sh[0]);
    }
}

extern "C" void kernel_launch(void* const* d_in, const int* in_sizes, int n_in,
                              void* d_out, int out_size) {
    const float* x   = (const float*)d_in[0];
    const float* emb = (const float*)d_in[1];
    float* out  = (float*)d_out;
    float* outq = out + 1;
    float2* enc = (float2*)(out + 2 + QELEMS);

    cudaFuncSetAttribute(argmin_fp16_kernel, cudaFuncAttributeMaxDynamicSharedMemorySize,
                         SMEM_BYTES);

    prep_kernel<<<8, 256>>>(emb);                           // 0
    split_x_kernel<<<1024, 256>>>(x);                       // 1
    split_e_kernel<<<32, 256>>>(emb);                       // 2
    argmin_fp16_kernel<<<512, 512, SMEM_BYTES>>>();         // 3 (profiled slot)
    brute_kernel<<<256, 256>>>(x, emb);                     // 4
    quantize_kernel<<<QELEMS / 256, 256>>>(x, emb, outq);   // 5
    hist_kernel<<<NPIX / 256, 256>>>();                     // 6
    enc_kernel<<<(NPIX * (K / 2)) / 256, 256>>>(enc);       // 7
    final_kernel<<<1, 256>>>(out);                          // 8
}

// round 11
// speedup vs baseline: 1.2845x; 1.2845x over previous
#include <cuda_runtime.h>
#include <cuda_fp16.h>
#include <cstdint>

#define D      256
#define K      2048
#define BHW    4096
#define NPIX   65536
#define QELEMS 16777216
#define MARGIN 0.075f

// ---------------- device scratch ----------------
// A scratch (hi only): [b*32+pt][px 128][c 32 (^= px&7)] uint4 (c = 8 halves of d)
__device__ uint4 g_xA[(size_t)512 * 128 * 32];          // 32 MB
// B scratch (hi only): [step 32][n 256][cl 8 (^= n&7)] uint4
__device__ uint4 g_xB[(size_t)32 * 256 * 8];            // 1 MB
__device__ float g_halfnorm[K];
__device__ int   g_idx[NPIX];
__device__ int   g_counts[K];
__device__ float g_loss;
__device__ int   g_ambig_cnt;
__device__ int   g_ambig[NPIX];

__device__ __forceinline__ void mma16(float* c, const uint32_t* a, const uint32_t* b) {
    asm volatile("mma.sync.aligned.m16n8k16.row.col.f32.f16.f16.f32 "
        "{%0,%1,%2,%3}, {%4,%5,%6,%7}, {%8,%9}, {%0,%1,%2,%3};"
        : "+f"(c[0]), "+f"(c[1]), "+f"(c[2]), "+f"(c[3])
        : "r"(a[0]), "r"(a[1]), "r"(a[2]), "r"(a[3]), "r"(b[0]), "r"(b[1]));
}
__device__ __forceinline__ void ldsm4(uint32_t* r, uint32_t addr) {
    asm volatile("ldmatrix.sync.aligned.m8n8.x4.shared.b16 {%0,%1,%2,%3}, [%4];"
        : "=r"(r[0]), "=r"(r[1]), "=r"(r[2]), "=r"(r[3]) : "r"(addr));
}
__device__ __forceinline__ uint32_t smem_u32(const void* p) {
    uint32_t a;
    asm("{ .reg .u64 t; cvta.to.shared.u64 t, %1; cvt.u32.u64 %0, t; }" : "=r"(a) : "l"(p));
    return a;
}
#define CPASYNC(dst, src) \
    asm volatile("cp.async.ca.shared.global [%0], [%1], 16;" :: "r"(dst), "l"(src))
#define CPCOMMIT() asm volatile("cp.async.commit_group;" ::: "memory")
#define CPWAIT0()  asm volatile("cp.async.wait_group 0;" ::: "memory")

__device__ __forceinline__ uint32_t packh2(float a, float b) {
    __half2 h2 = __halves2half2(__float2half_rn(a), __float2half_rn(b));
    return *reinterpret_cast<uint32_t*>(&h2);
}

// ---------------- kernel 0: halfnorm + zero counters ----------------
__global__ void prep_kernel(const float* __restrict__ emb) {
    int k = blockIdx.x * blockDim.x + threadIdx.x;
    if (k < K) {
        const float4* row = reinterpret_cast<const float4*>(emb + (size_t)k * D);
        float s = 0.f;
        #pragma unroll
        for (int i = 0; i < D / 4; i++) {
            float4 v = row[i];
            s += v.x * v.x + v.y * v.y + v.z * v.z + v.w * v.w;
        }
        g_halfnorm[k] = 0.5f * s;
        g_counts[k] = 0;
        if (k == 0) { g_loss = 0.f; g_ambig_cnt = 0; }
    }
}

// ---------------- kernel 1: -x -> fp16 hi, ldmatrix-ready A scratch ----------------
__global__ void split_x_kernel(const float* __restrict__ x) {
    __shared__ uint4 stg[64 * 32];   // [pxl][cs]
    int blk = blockIdx.x;
    int b = blk >> 6, pt = (blk >> 1) & 31, hpx = blk & 1;
    int tid = threadIdx.x;
    int hw0 = pt * 128 + hpx * 64;

    #pragma unroll
    for (int it = 0; it < 8; it++) {
        int id = tid + it * 256;
        int pxl = id & 63, c = id >> 6;
        float v[8];
        #pragma unroll
        for (int j = 0; j < 8; j++)
            v[j] = -x[((size_t)(b * 256 + c * 8 + j)) * 4096 + hw0 + pxl];
        uint4 hi;
        hi.x = packh2(v[0], v[1]); hi.y = packh2(v[2], v[3]);
        hi.z = packh2(v[4], v[5]); hi.w = packh2(v[6], v[7]);
        stg[pxl * 32 + (c ^ (pxl & 7))] = hi;
    }
    __syncthreads();
    size_t ob = (size_t)(blk >> 1) * 4096;
    #pragma unroll
    for (int it = 0; it < 8; it++) {
        int id = tid + it * 256;
        int pxl = id >> 5, cp = id & 31;
        g_xA[ob + (size_t)(hpx * 64 + pxl) * 32 + cp] = stg[pxl * 32 + cp];
    }
}

// ---------------- kernel 2: e -> fp16 hi, ldmatrix-ready B scratch ----------------
__global__ void split_e_kernel(const float* __restrict__ emb) {
    __shared__ uint4 stg[64 * 32];   // [nl][cs]
    int n0 = blockIdx.x * 64;
    int tid = threadIdx.x;
    #pragma unroll
    for (int it = 0; it < 8; it++) {
        int id = tid + it * 256;
        int c = id & 31, nl = id >> 5;
        float v[8];
        #pragma unroll
        for (int j = 0; j < 8; j++)
            v[j] = emb[(size_t)(n0 + nl) * D + c * 8 + j];
        uint4 hi;
        hi.x = packh2(v[0], v[1]); hi.y = packh2(v[2], v[3]);
        hi.z = packh2(v[4], v[5]); hi.w = packh2(v[6], v[7]);
        int s = c >> 3, cl = c & 7;
        stg[nl * 32 + s * 8 + (cl ^ (nl & 7))] = hi;
    }
    __syncthreads();
    int nt = n0 >> 8;
    #pragma unroll
    for (int it = 0; it < 8; it++) {
        int id = tid + it * 256;        // [s 4][nl 64][clp 8]
        int clp = id & 7, nl = (id >> 3) & 63, s = id >> 9;
        g_xB[((size_t)(nt * 4 + s) * 256 + (n0 & 255) + nl) * 8 + clp] =
            stg[nl * 32 + s * 8 + clp];
    }
}

// ---------------- kernel 3: fp16-hi screening GEMM + top2 argmin ----------------
#define BOFF   65536
#define SRVW   32768
#define SR2W   33280
#define SRIW   33792
#define SMEM_BYTES 137216

__global__ __launch_bounds__(512, 1) void argmin_fp16_kernel() {
    extern __shared__ uint4 sm4[];
    uint32_t sb = smem_u32(sm4);
    uint32_t* smw = reinterpret_cast<uint32_t*>(sm4);
    float* srv = reinterpret_cast<float*>(smw + SRVW);
    float* sr2 = reinterpret_cast<float*>(smw + SR2W);
    int*   sri = reinterpret_cast<int*>(smw + SRIW);

    int tid = threadIdx.x;
    int w = tid >> 5, lane = tid & 31;
    int warpM = w >> 2, warpN = w & 3;        // 4 x 4 warps; tile 32px x 64n
    int g = lane >> 2, tig = lane & 3;

    srv[tid] = 3.4e38f; sr2[tid] = 3.4e38f; sri[tid] = 0;

    {
        const uint4* asrc = &g_xA[(size_t)blockIdx.x * 4096];
        #pragma unroll
        for (int i = 0; i < 8; i++) {
            int id = tid + i * 512;
            CPASYNC(sb + id * 16, asrc + id);
        }
        #pragma unroll
        for (int i = 0; i < 4; i++) {
            int id = tid + i * 512;
            CPASYNC(sb + BOFF + id * 16, &g_xB[id]);
        }
        CPCOMMIT();
        CPWAIT0();
    }

    int pxA0 = warpM * 32 + (lane & 15);
    int kcA  = lane >> 4;
    int nB0  = warpN * 64 + (lane & 7) + ((lane >> 4) << 3);
    int kcB  = (lane >> 3) & 1;

    float acc[2][8][4];

    for (int nt = 0; nt < 8; nt++) {
        #pragma unroll
        for (int mf = 0; mf < 2; mf++)
            #pragma unroll
            for (int nf = 0; nf < 8; nf++)
                #pragma unroll
                for (int i = 0; i < 4; i++) acc[mf][nf][i] = 0.f;

        for (int s = 0; s < 4; s++) {
            int step = nt * 4 + s;
            int buf = step & 1;
            __syncthreads();
            if (step < 31) {
                const uint4* bsrc = &g_xB[(size_t)(step + 1) * 2048];
                uint32_t bdst = sb + BOFF + (buf ^ 1) * 32768;
                #pragma unroll
                for (int i = 0; i < 4; i++) {
                    int id = tid + i * 512;
                    CPASYNC(bdst + id * 16, bsrc + id);
                }
                CPCOMMIT();
            }
            uint32_t bbase = sb + BOFF + buf * 32768;
            #pragma unroll
            for (int kb = 0; kb < 4; kb++) {
                int cA = s * 8 + kb * 2 + kcA;
                uint32_t ah[2][4];
                #pragma unroll
                for (int mf = 0; mf < 2; mf++) {
                    int px = pxA0 + mf * 16;
                    uint32_t ro = (uint32_t)(px * 32 + (cA ^ (px & 7))) * 16;
                    ldsm4(ah[mf], sb + ro);
                }
                int clB = kb * 2 + kcB;
                uint32_t bh[4][4];
                #pragma unroll
                for (int p = 0; p < 4; p++) {
                    int n = nB0 + p * 16;
                    uint32_t ro = (uint32_t)(n * 8 + (clB ^ (n & 7))) * 16;
                    ldsm4(bh[p], bbase + ro);
                }
                #pragma unroll
                for (int mf = 0; mf < 2; mf++)
                    #pragma unroll
                    for (int nf = 0; nf < 8; nf++)
                        mma16(acc[mf][nf], ah[mf], &bh[nf >> 1][(nf & 1) * 2]);
            }
            CPWAIT0();
        }
        float hn[8][2];
        int colbase = nt * 256 + warpN * 64 + tig * 2;
        #pragma unroll
        for (int nf = 0; nf < 8; nf++) {
            hn[nf][0] = __ldg(&g_halfnorm[colbase + nf * 8]);
            hn[nf][1] = __ldg(&g_halfnorm[colbase + nf * 8 + 1]);
        }
        #pragma unroll
        for (int mf = 0; mf < 2; mf++) {
            #pragma unroll
            for (int half = 0; half < 2; half++) {
                float v = 3.4e38f, v2 = 3.4e38f; int vi = 0;
                #pragma unroll
                for (int nf = 0; nf < 8; nf++) {
                    #pragma unroll
                    for (int c = 0; c < 2; c++) {
                        float sc = acc[mf][nf][half * 2 + c] + hn[nf][c];
                        int ci = colbase + nf * 8 + c;
                        if (sc < v) { v2 = v; v = sc; vi = ci; }
                        else if (sc < v2) { v2 = sc; }
                    }
                }
                #pragma unroll
                for (int o = 1; o <= 2; o <<= 1) {
                    float ov  = __shfl_xor_sync(0xffffffffu, v, o);
                    int   oi  = __shfl_xor_sync(0xffffffffu, vi, o);
                    float ov2 = __shfl_xor_sync(0xffffffffu, v2, o);
                    float nv2 = fminf(fmaxf(v, ov), fminf(v2, ov2));
                    bool take = (ov < v) || (ov == v && oi < vi);
                    if (take) { v = ov; vi = oi; }
                    v2 = nv2;
                }
                if (tig == 0) {
                    int row = warpM * 32 + mf * 16 + half * 8 + g;
                    int slot = row * 4 + warpN;
                    float sv = srv[slot], sv2 = sr2[slot]; int si = sri[slot];
                    float nv2 = fminf(fmaxf(v, sv), fminf(v2, sv2));
                    bool take = (v < sv) || (v == sv && vi < si);
                    srv[slot] = take ? v : sv;
                    sri[slot] = take ? vi : si;
                    sr2[slot] = nv2;
                }
            }
        }
    }
    __syncthreads();
    if (tid < 128) {
        float v = srv[tid * 4], v2 = sr2[tid * 4]; int vi = sri[tid * 4];
        #pragma unroll
        for (int ww = 1; ww < 4; ww++) {
            float ov = srv[tid * 4 + ww], ov2 = sr2[tid * 4 + ww];
            int oi = sri[tid * 4 + ww];
            float nv2 = fminf(fmaxf(v, ov), fminf(v2, ov2));
            bool take = (ov < v) || (ov == v && oi < vi);
            if (take) { v = ov; vi = oi; }
            v2 = nv2;
        }
        int n = blockIdx.x * 128 + tid;
        g_idx[n] = vi;
        if (v2 - v < MARGIN) {
            int pos = atomicAdd(&g_ambig_cnt, 1);
            g_ambig[pos] = n;
        }
    }
}

// ---------------- kernel 4: exact fp32 brute force (coalesced, 16 px / pass) ----------------
#define BPX 16
__global__ __launch_bounds__(256, 2) void brute_kernel(const float* __restrict__ x,
                                                       const float* __restrict__ emb) {
    __shared__ float sx[BPX][256];
    __shared__ float wv[BPX][8];
    __shared__ int   wi[BPX][8];
    int tid = threadIdx.x;
    int lane = tid & 31, wrp = tid >> 5;
    int seg = tid & 7, kg = tid >> 3;       // 32 k-groups x 8 segs
    int count = g_ambig_cnt;

    for (int base = blockIdx.x * BPX; base < count; base += gridDim.x * BPX) {
        __syncthreads();
        for (int i = tid; i < BPX * 256; i += 256) {
            int px = i >> 8, d = i & 255;
            int li = base + px;
            int n = g_ambig[li < count ? li : count - 1];
            sx[px][d] = x[(((size_t)(n >> 12) * 256 + d) << 12) | (uint32_t)(n & 4095)];
        }
        __syncthreads();
        float best[BPX]; int bik[BPX];
        #pragma unroll
        for (int p = 0; p < BPX; p++) { best[p] = 3.4e38f; bik[p] = 0; }

        for (int kt = 0; kt < 64; kt++) {
            int k = kt * 32 + kg;
            const float4* er = reinterpret_cast<const float4*>(emb + (size_t)k * 256);
            float4 e[8];
            #pragma unroll
            for (int c = 0; c < 8; c++) e[c] = er[c * 8 + seg];   // coalesced 128B per k-row
            float hn = g_halfnorm[k];
            #pragma unroll
            for (int p = 0; p < BPX; p++) {
                float dot = 0.f;
                #pragma unroll
                for (int c = 0; c < 8; c++) {
                    const float* xs = &sx[p][c * 32 + seg * 4];
                    dot = fmaf(xs[0], e[c].x, dot);
                    dot = fmaf(xs[1], e[c].y, dot);
                    dot = fmaf(xs[2], e[c].z, dot);
                    dot = fmaf(xs[3], e[c].w, dot);
                }
                dot += __shfl_xor_sync(0xffffffffu, dot, 1);
                dot += __shfl_xor_sync(0xffffffffu, dot, 2);
                dot += __shfl_xor_sync(0xffffffffu, dot, 4);
                float sc = hn - dot;
                if (sc < best[p]) { best[p] = sc; bik[p] = k; }   // k ascending -> lowest idx
            }
        }
        // warp-level: fold the 4 k-groups within this warp (lanes differ by 8, 16)
        #pragma unroll
        for (int p = 0; p < BPX; p++) {
            float v = best[p]; int vi = bik[p];
            #pragma unroll
            for (int o = 8; o <= 16; o <<= 1) {
                float ov = __shfl_xor_sync(0xffffffffu, v, o);
                int   oi = __shfl_xor_sync(0xffffffffu, vi, o);
                if (ov < v || (ov == v && oi < vi)) { v = ov; vi = oi; }
            }
            if (lane == 0) { wv[p][wrp] = v; wi[p][wrp] = vi; }
        }
        __syncthreads();
        if (tid < BPX * 8) {
            int p = tid >> 3, wq = tid & 7;
            float v = wv[p][wq]; int vi = wi[p][wq];
            #pragma unroll
            for (int o = 1; o < 8; o <<= 1) {
                float ov = __shfl_xor_sync(0xffffffffu, v, o);
                int   oi = __shfl_xor_sync(0xffffffffu, vi, o);
                if (ov < v || (ov == v && oi < vi)) { v = ov; vi = oi; }
            }
            if (wq == 0) {
                int li = base + p;
                if (li < count) g_idx[g_ambig[li]] = vi;
            }
        }
    }
}

// ---------------- kernel 5: gather quantized + loss partials ----------------
__global__ void quantize_kernel(const float* __restrict__ x,
                                const float* __restrict__ emb,
                                float* __restrict__ outq) {
    int o = blockIdx.x * 256 + threadIdx.x;
    int hw = o & (BHW - 1);
    int d  = (o >> 12) & (D - 1);
    int b  = o >> 20;
    int n  = (b << 12) | hw;
    int k  = g_idx[n];
    float q  = __ldg(emb + (size_t)k * D + d);
    float xv = x[o];
    __stcs(outq + o, q);
    float diff = q - xv;
    float l = diff * diff;
    #pragma unroll
    for (int off = 16; off; off >>= 1) l += __shfl_xor_sync(0xffffffffu, l, off);
    __shared__ float ls[8];
    int lane = threadIdx.x & 31, w = threadIdx.x >> 5;
    if (lane == 0) ls[w] = l;
    __syncthreads();
    if (threadIdx.x == 0) {
        float ssum = 0.f;
        #pragma unroll
        for (int i = 0; i < 8; i++) ssum += ls[i];
        atomicAdd(&g_loss, ssum);
    }
}

// ---------------- kernel 6: histogram ----------------
__global__ void hist_kernel() {
    int n = blockIdx.x * 256 + threadIdx.x;
    atomicAdd(&g_counts[g_idx[n]], 1);
}

// ---------------- kernel 7: one-hot encodings ----------------
__global__ void enc_kernel(float2* __restrict__ enc) {
    int i2 = blockIdx.x * 256 + threadIdx.x;
    int n = i2 >> 10;
    int j = (i2 & 1023) << 1;
    int k = g_idx[n];
    float2 v;
    v.x = (j == k)     ? 1.f : 0.f;
    v.y = (j + 1 == k) ? 1.f : 0.f;
    __stcs(enc + i2, v);
}

// ---------------- kernel 8: scalars ----------------
__global__ void final_kernel(float* __restrict__ out) {
    __shared__ float sh[256];
    int t = threadIdx.x;
    float s = 0.f;
    for (int k = t; k < K; k += 256) {
        float p = (float)g_counts[k] * (1.0f / (float)NPIX);
        s += p * logf(p + 1e-10f);
    }
    sh[t] = s;
    __syncthreads();
    for (int o = 128; o; o >>= 1) {
        if (t < o) sh[t] += sh[t + o];
        __syncthreads();
    }
    if (t == 0) {
        out[0] = 0.25f * g_loss / (float)QELEMS;
        out[1 + QELEMS] = expf(-sh[0]);
    }
}

extern "C" void kernel_launch(void* const* d_in, const int* in_sizes, int n_in,
                              void* d_out, int out_size) {
    const float* x   = (const float*)d_in[0];
    const float* emb = (const float*)d_in[1];
    float* out  = (float*)d_out;
    float* outq = out + 1;
    float2* enc = (float2*)(out + 2 + QELEMS);

    cudaFuncSetAttribute(argmin_fp16_kernel, cudaFuncAttributeMaxDynamicSharedMemorySize,
                         SMEM_BYTES);

    prep_kernel<<<8, 256>>>(emb);                           // 0
    split_x_kernel<<<1024, 256>>>(x);                       // 1
    split_e_kernel<<<32, 256>>>(emb);                       // 2
    argmin_fp16_kernel<<<512, 512, SMEM_BYTES>>>();         // 3 (profiled slot)
    brute_kernel<<<148, 256>>>(x, emb);                     // 4
    quantize_kernel<<<QELEMS / 256, 256>>>(x, emb, outq);   // 5
    hist_kernel<<<NPIX / 256, 256>>>();                     // 6
    enc_kernel<<<(NPIX * (K / 2)) / 256, 256>>>(enc);       // 7
    final_kernel<<<1, 256>>>(out);                          // 8
}

// round 12
// speedup vs baseline: 1.3804x; 1.0747x over previous
#include <cuda_runtime.h>
#include <cuda_fp16.h>
#include <cstdint>

#define D      256
#define K      2048
#define BHW    4096
#define NPIX   65536
#define QELEMS 16777216
#define MARGIN 0.075f

// ---------------- device scratch ----------------
// A scratch (hi only): [b*32+pt][px 128][c 32 (^= px&7)] uint4 (c = 8 halves of d)
__device__ uint4 g_xA[(size_t)512 * 128 * 32];          // 32 MB
// B scratch (hi only): [step 16][n 256][cl 16 (low3 ^= n&7)] uint4
__device__ uint4 g_xB[(size_t)16 * 256 * 16];           // 1 MB
__device__ float g_halfnorm[K];
__device__ int   g_idx[NPIX];
__device__ int   g_counts[K];
__device__ float g_loss;
__device__ int   g_ambig_cnt;
__device__ int   g_ambig[NPIX];

__device__ __forceinline__ void mma16(float* c, const uint32_t* a, const uint32_t* b) {
    asm volatile("mma.sync.aligned.m16n8k16.row.col.f32.f16.f16.f32 "
        "{%0,%1,%2,%3}, {%4,%5,%6,%7}, {%8,%9}, {%0,%1,%2,%3};"
        : "+f"(c[0]), "+f"(c[1]), "+f"(c[2]), "+f"(c[3])
        : "r"(a[0]), "r"(a[1]), "r"(a[2]), "r"(a[3]), "r"(b[0]), "r"(b[1]));
}
__device__ __forceinline__ void ldsm4(uint32_t* r, uint32_t addr) {
    asm volatile("ldmatrix.sync.aligned.m8n8.x4.shared.b16 {%0,%1,%2,%3}, [%4];"
        : "=r"(r[0]), "=r"(r[1]), "=r"(r[2]), "=r"(r[3]) : "r"(addr));
}
__device__ __forceinline__ uint32_t smem_u32(const void* p) {
    uint32_t a;
    asm("{ .reg .u64 t; cvta.to.shared.u64 t, %1; cvt.u32.u64 %0, t; }" : "=r"(a) : "l"(p));
    return a;
}
#define CPASYNC(dst, src) \
    asm volatile("cp.async.ca.shared.global [%0], [%1], 16;" :: "r"(dst), "l"(src))
#define CPCOMMIT() asm volatile("cp.async.commit_group;" ::: "memory")
#define CPWAIT0()  asm volatile("cp.async.wait_group 0;" ::: "memory")

__device__ __forceinline__ uint32_t packh2(float a, float b) {
    __half2 h2 = __halves2half2(__float2half_rn(a), __float2half_rn(b));
    return *reinterpret_cast<uint32_t*>(&h2);
}

// ---------------- kernel 0: halfnorm + zero counters ----------------
__global__ void prep_kernel(const float* __restrict__ emb) {
    int k = blockIdx.x * blockDim.x + threadIdx.x;
    if (k < K) {
        const float4* row = reinterpret_cast<const float4*>(emb + (size_t)k * D);
        float s = 0.f;
        #pragma unroll
        for (int i = 0; i < D / 4; i++) {
            float4 v = row[i];
            s += v.x * v.x + v.y * v.y + v.z * v.z + v.w * v.w;
        }
        g_halfnorm[k] = 0.5f * s;
        g_counts[k] = 0;
        if (k == 0) { g_loss = 0.f; g_ambig_cnt = 0; }
    }
}

// ---------------- kernel 1: -x -> fp16 hi, ldmatrix-ready A scratch ----------------
__global__ void split_x_kernel(const float* __restrict__ x) {
    __shared__ uint4 stg[64 * 32];   // [pxl][cs]
    int blk = blockIdx.x;
    int b = blk >> 6, pt = (blk >> 1) & 31, hpx = blk & 1;
    int tid = threadIdx.x;
    int hw0 = pt * 128 + hpx * 64;

    #pragma unroll
    for (int it = 0; it < 8; it++) {
        int id = tid + it * 256;
        int pxl = id & 63, c = id >> 6;
        float v[8];
        #pragma unroll
        for (int j = 0; j < 8; j++)
            v[j] = -x[((size_t)(b * 256 + c * 8 + j)) * 4096 + hw0 + pxl];
        uint4 hi;
        hi.x = packh2(v[0], v[1]); hi.y = packh2(v[2], v[3]);
        hi.z = packh2(v[4], v[5]); hi.w = packh2(v[6], v[7]);
        stg[pxl * 32 + (c ^ (pxl & 7))] = hi;
    }
    __syncthreads();
    size_t ob = (size_t)(blk >> 1) * 4096;
    #pragma unroll
    for (int it = 0; it < 8; it++) {
        int id = tid + it * 256;
        int pxl = id >> 5, cp = id & 31;
        g_xA[ob + (size_t)(hpx * 64 + pxl) * 32 + cp] = stg[pxl * 32 + cp];
    }
}

// ---------------- kernel 2: e -> fp16 hi, ldmatrix-ready B scratch ----------------
// B scratch: [step 16 (128d each)][n 256][cl 16], cl low-3 XOR n&7
__global__ void split_e_kernel(const float* __restrict__ emb) {
    __shared__ uint4 stg[64 * 32];   // [nl][s*16 + swz(cl)]
    int n0 = blockIdx.x * 64;
    int tid = threadIdx.x;
    #pragma unroll
    for (int it = 0; it < 8; it++) {
        int id = tid + it * 256;
        int c = id & 31, nl = id >> 5;
        float v[8];
        #pragma unroll
        for (int j = 0; j < 8; j++)
            v[j] = emb[(size_t)(n0 + nl) * D + c * 8 + j];
        uint4 hi;
        hi.x = packh2(v[0], v[1]); hi.y = packh2(v[2], v[3]);
        hi.z = packh2(v[4], v[5]); hi.w = packh2(v[6], v[7]);
        int s = c >> 4, cl = c & 15;
        stg[nl * 32 + s * 16 + (cl ^ (nl & 7))] = hi;
    }
    __syncthreads();
    int nt = n0 >> 8;
    #pragma unroll
    for (int it = 0; it < 8; it++) {
        int id = tid + it * 256;        // [s 2][nl 64][clp 16]
        int clp = id & 15, nl = (id >> 4) & 63, s = id >> 10;
        g_xB[((size_t)(nt * 2 + s) * 256 + (n0 & 255) + nl) * 16 + clp] =
            stg[nl * 32 + s * 16 + clp];
    }
}

// ---------------- kernel 3: fp16-hi screening GEMM + top2 argmin ----------------
// smem: A[128][32]u4 = 64KB | B[2buf][256][16]u4 = 128KB | srv/sr2/sri 6KB
#define BOFF   65536
#define BUFSZ  65536
#define SRVW   49152
#define SR2W   49664
#define SRIW   50176
#define SMEM_BYTES 202752

__global__ __launch_bounds__(512, 1) void argmin_fp16_kernel() {
    extern __shared__ uint4 sm4[];
    uint32_t sb = smem_u32(sm4);
    uint32_t* smw = reinterpret_cast<uint32_t*>(sm4);
    float* srv = reinterpret_cast<float*>(smw + SRVW);
    float* sr2 = reinterpret_cast<float*>(smw + SR2W);
    int*   sri = reinterpret_cast<int*>(smw + SRIW);

    int tid = threadIdx.x;
    int w = tid >> 5, lane = tid & 31;
    int warpM = w >> 2, warpN = w & 3;        // 4 x 4 warps; tile 32px x 64n
    int g = lane >> 2, tig = lane & 3;

    srv[tid] = 3.4e38f; sr2[tid] = 3.4e38f; sri[tid] = 0;

    // prologue: A resident (8/thread) + B step0 (8/thread)
    {
        const uint4* asrc = &g_xA[(size_t)blockIdx.x * 4096];
        #pragma unroll
        for (int i = 0; i < 8; i++) {
            int id = tid + i * 512;
            CPASYNC(sb + id * 16, asrc + id);
        }
        #pragma unroll
        for (int i = 0; i < 8; i++) {
            int id = tid + i * 512;
            CPASYNC(sb + BOFF + id * 16, &g_xB[id]);
        }
        CPCOMMIT();
        CPWAIT0();
    }

    int pxA0 = warpM * 32 + (lane & 15);
    int kcA  = lane >> 4;
    int nB0  = warpN * 64 + (lane & 7) + ((lane >> 4) << 3);
    int kcB  = (lane >> 3) & 1;

    float acc[2][8][4];

    for (int nt = 0; nt < 8; nt++) {
        #pragma unroll
        for (int mf = 0; mf < 2; mf++)
            #pragma unroll
            for (int nf = 0; nf < 8; nf++)
                #pragma unroll
                for (int i = 0; i < 4; i++) acc[mf][nf][i] = 0.f;

        for (int s = 0; s < 2; s++) {          // 128-d slices
            int step = nt * 2 + s;
            int buf = step & 1;
            __syncthreads();
            if (step < 15) {
                const uint4* bsrc = &g_xB[(size_t)(step + 1) * 4096];
                uint32_t bdst = sb + BOFF + (buf ^ 1) * BUFSZ;
                #pragma unroll
                for (int i = 0; i < 8; i++) {
                    int id = tid + i * 512;
                    CPASYNC(bdst + id * 16, bsrc + id);
                }
                CPCOMMIT();
            }
            uint32_t bbase = sb + BOFF + buf * BUFSZ;
            #pragma unroll
            for (int kb = 0; kb < 8; kb++) {
                int cA = s * 16 + kb * 2 + kcA;
                uint32_t ah[2][4];
                #pragma unroll
                for (int mf = 0; mf < 2; mf++) {
                    int px = pxA0 + mf * 16;
                    uint32_t ro = (uint32_t)(px * 32 + (cA ^ (px & 7))) * 16;
                    ldsm4(ah[mf], sb + ro);
                }
                int clB = kb * 2 + kcB;
                uint32_t bh[4][4];
                #pragma unroll
                for (int p = 0; p < 4; p++) {
                    int n = nB0 + p * 16;
                    uint32_t ro = (uint32_t)(n * 16 + (clB ^ (n & 7))) * 16;
                    ldsm4(bh[p], bbase + ro);
                }
                #pragma unroll
                for (int mf = 0; mf < 2; mf++)
                    #pragma unroll
                    for (int nf = 0; nf < 8; nf++)
                        mma16(acc[mf][nf], ah[mf], &bh[nf >> 1][(nf & 1) * 2]);
            }
            CPWAIT0();
        }
        float hn[8][2];
        int colbase = nt * 256 + warpN * 64 + tig * 2;
        #pragma unroll
        for (int nf = 0; nf < 8; nf++) {
            hn[nf][0] = __ldg(&g_halfnorm[colbase + nf * 8]);
            hn[nf][1] = __ldg(&g_halfnorm[colbase + nf * 8 + 1]);
        }
        #pragma unroll
        for (int mf = 0; mf < 2; mf++) {
            #pragma unroll
            for (int half = 0; half < 2; half++) {
                float v = 3.4e38f, v2 = 3.4e38f; int vi = 0;
                #pragma unroll
                for (int nf = 0; nf < 8; nf++) {
                    #pragma unroll
                    for (int c = 0; c < 2; c++) {
                        float sc = acc[mf][nf][half * 2 + c] + hn[nf][c];
                        int ci = colbase + nf * 8 + c;
                        if (sc < v) { v2 = v; v = sc; vi = ci; }
                        else if (sc < v2) { v2 = sc; }
                    }
                }
                #pragma unroll
                for (int o = 1; o <= 2; o <<= 1) {
                    float ov  = __shfl_xor_sync(0xffffffffu, v, o);
                    int   oi  = __shfl_xor_sync(0xffffffffu, vi, o);
                    float ov2 = __shfl_xor_sync(0xffffffffu, v2, o);
                    float nv2 = fminf(fmaxf(v, ov), fminf(v2, ov2));
                    bool take = (ov < v) || (ov == v && oi < vi);
                    if (take) { v = ov; vi = oi; }
                    v2 = nv2;
                }
                if (tig == 0) {
                    int row = warpM * 32 + mf * 16 + half * 8 + g;
                    int slot = row * 4 + warpN;
                    float sv = srv[slot], sv2 = sr2[slot]; int si = sri[slot];
                    float nv2 = fminf(fmaxf(v, sv), fminf(v2, sv2));
                    bool take = (v < sv) || (v == sv && vi < si);
                    srv[slot] = take ? v : sv;
                    sri[slot] = take ? vi : si;
                    sr2[slot] = nv2;
                }
            }
        }
    }
    __syncthreads();
    if (tid < 128) {
        float v = srv[tid * 4], v2 = sr2[tid * 4]; int vi = sri[tid * 4];
        #pragma unroll
        for (int ww = 1; ww < 4; ww++) {
            float ov = srv[tid * 4 + ww], ov2 = sr2[tid * 4 + ww];
            int oi = sri[tid * 4 + ww];
            float nv2 = fminf(fmaxf(v, ov), fminf(v2, ov2));
            bool take = (ov < v) || (ov == v && oi < vi);
            if (take) { v = ov; vi = oi; }
            v2 = nv2;
        }
        int n = blockIdx.x * 128 + tid;
        g_idx[n] = vi;
        if (v2 - v < MARGIN) {
            int pos = atomicAdd(&g_ambig_cnt, 1);
            g_ambig[pos] = n;
        }
    }
}

// ---------------- kernel 4: exact fp32 brute force (coalesced, 16 px / pass) ----------------
#define BPX 16
__global__ __launch_bounds__(256, 2) void brute_kernel(const float* __restrict__ x,
                                                       const float* __restrict__ emb) {
    __shared__ float sx[BPX][256];
    __shared__ float wv[BPX][8];
    __shared__ int   wi[BPX][8];
    int tid = threadIdx.x;
    int lane = tid & 31, wrp = tid >> 5;
    int seg = tid & 7, kg = tid >> 3;       // 32 k-groups x 8 segs
    int count = g_ambig_cnt;

    for (int base = blockIdx.x * BPX; base < count; base += gridDim.x * BPX) {
        __syncthreads();
        for (int i = tid; i < BPX * 256; i += 256) {
            int px = i >> 8, d = i & 255;
            int li = base + px;
            int n = g_ambig[li < count ? li : count - 1];
            sx[px][d] = x[(((size_t)(n >> 12) * 256 + d) << 12) | (uint32_t)(n & 4095)];
        }
        __syncthreads();
        float best[BPX]; int bik[BPX];
        #pragma unroll
        for (int p = 0; p < BPX; p++) { best[p] = 3.4e38f; bik[p] = 0; }

        for (int kt = 0; kt < 64; kt++) {
            int k = kt * 32 + kg;
            const float4* er = reinterpret_cast<const float4*>(emb + (size_t)k * 256);
            float4 e[8];
            #pragma unroll
            for (int c = 0; c < 8; c++) e[c] = er[c * 8 + seg];
            float hn = g_halfnorm[k];
            #pragma unroll
            for (int p = 0; p < BPX; p++) {
                float dot = 0.f;
                #pragma unroll
                for (int c = 0; c < 8; c++) {
                    const float* xs = &sx[p][c * 32 + seg * 4];
                    dot = fmaf(xs[0], e[c].x, dot);
                    dot = fmaf(xs[1], e[c].y, dot);
                    dot = fmaf(xs[2], e[c].z, dot);
                    dot = fmaf(xs[3], e[c].w, dot);
                }
                dot += __shfl_xor_sync(0xffffffffu, dot, 1);
                dot += __shfl_xor_sync(0xffffffffu, dot, 2);
                dot += __shfl_xor_sync(0xffffffffu, dot, 4);
                float sc = hn - dot;
                if (sc < best[p]) { best[p] = sc; bik[p] = k; }
            }
        }
        #pragma unroll
        for (int p = 0; p < BPX; p++) {
            float v = best[p]; int vi = bik[p];
            #pragma unroll
            for (int o = 8; o <= 16; o <<= 1) {
                float ov = __shfl_xor_sync(0xffffffffu, v, o);
                int   oi = __shfl_xor_sync(0xffffffffu, vi, o);
                if (ov < v || (ov == v && oi < vi)) { v = ov; vi = oi; }
            }
            if (lane == 0) { wv[p][wrp] = v; wi[p][wrp] = vi; }
        }
        __syncthreads();
        if (tid < BPX * 8) {
            int p = tid >> 3, wq = tid & 7;
            float v = wv[p][wq]; int vi = wi[p][wq];
            #pragma unroll
            for (int o = 1; o < 8; o <<= 1) {
                float ov = __shfl_xor_sync(0xffffffffu, v, o);
                int   oi = __shfl_xor_sync(0xffffffffu, vi, o);
                if (ov < v || (ov == v && oi < vi)) { v = ov; vi = oi; }
            }
            if (wq == 0) {
                int li = base + p;
                if (li < count) g_idx[g_ambig[li]] = vi;
            }
        }
    }
}

// ---------------- kernel 5: transposed coalesced gather + loss ----------------
// block = 32 pixels x 256 d; gather emb rows coalesced, write [B,C,H,W] coalesced
__global__ __launch_bounds__(256) void quantize_kernel(const float* __restrict__ x,
                                                       const float* __restrict__ emb,
                                                       float* __restrict__ outq) {
    __shared__ float sq[32 * 257];
    __shared__ int   sk[32];
    __shared__ float ls[8];
    int tid = threadIdx.x;
    int n0 = blockIdx.x * 32;
    int b = n0 >> 12, hw0 = n0 & 4095;
    if (tid < 32) sk[tid] = g_idx[n0 + tid];
    __syncthreads();
    #pragma unroll 8
    for (int j = 0; j < 32; j++) {
        sq[j * 257 + tid] = __ldg(emb + (size_t)sk[j] * 256 + tid);
    }
    __syncthreads();
    float l = 0.f;
    int dr = tid >> 5, px = tid & 31;
    #pragma unroll 8
    for (int j = 0; j < 32; j++) {
        int d = j * 8 + dr;
        size_t o = ((size_t)(b * 256 + d)) * 4096 + hw0 + px;
        float q = sq[px * 257 + d];
        float xv = x[o];
        __stcs(outq + o, q);
        float diff = q - xv;
        l += diff * diff;
    }
    #pragma unroll
    for (int off = 16; off; off >>= 1) l += __shfl_xor_sync(0xffffffffu, l, off);
    int lane = tid & 31, wq = tid >> 5;
    if (lane == 0) ls[wq] = l;
    __syncthreads();
    if (tid == 0) {
        float ssum = 0.f;
        #pragma unroll
        for (int i = 0; i < 8; i++) ssum += ls[i];
        atomicAdd(&g_loss, ssum);
    }
}

// ---------------- kernel 6: histogram ----------------
__global__ void hist_kernel() {
    int n = blockIdx.x * 256 + threadIdx.x;
    atomicAdd(&g_counts[g_idx[n]], 1);
}

// ---------------- kernel 7: one-hot encodings ----------------
__global__ void enc_kernel(float2* __restrict__ enc) {
    int i2 = blockIdx.x * 256 + threadIdx.x;
    int n = i2 >> 10;
    int j = (i2 & 1023) << 1;
    int k = g_idx[n];
    float2 v;
    v.x = (j == k)     ? 1.f : 0.f;
    v.y = (j + 1 == k) ? 1.f : 0.f;
    __stcs(enc + i2, v);
}

// ---------------- kernel 8: scalars ----------------
__global__ void final_kernel(float* __restrict__ out) {
    __shared__ float sh[256];
    int t = threadIdx.x;
    float s = 0.f;
    for (int k = t; k < K; k += 256) {
        float p = (float)g_counts[k] * (1.0f / (float)NPIX);
        s += p * logf(p + 1e-10f);
    }
    sh[t] = s;
    __syncthreads();
    for (int o = 128; o; o >>= 1) {
        if (t < o) sh[t] += sh[t + o];
        __syncthreads();
    }
    if (t == 0) {
        out[0] = 0.25f * g_loss / (float)QELEMS;
        out[1 + QELEMS] = expf(-sh[0]);
    }
}

extern "C" void kernel_launch(void* const* d_in, const int* in_sizes, int n_in,
                              void* d_out, int out_size) {
    const float* x   = (const float*)d_in[0];
    const float* emb = (const float*)d_in[1];
    float* out  = (float*)d_out;
    float* outq = out + 1;
    float2* enc = (float2*)(out + 2 + QELEMS);

    cudaFuncSetAttribute(argmin_fp16_kernel, cudaFuncAttributeMaxDynamicSharedMemorySize,
                         SMEM_BYTES);

    prep_kernel<<<8, 256>>>(emb);                           // 0
    split_x_kernel<<<1024, 256>>>(x);                       // 1
    split_e_kernel<<<32, 256>>>(emb);                       // 2
    argmin_fp16_kernel<<<512, 512, SMEM_BYTES>>>();         // 3 (profiled slot)
    brute_kernel<<<148, 256>>>(x, emb);                     // 4
    quantize_kernel<<<NPIX / 32, 256>>>(x, emb, outq);      // 5
    hist_kernel<<<NPIX / 256, 256>>>();                     // 6
    enc_kernel<<<(NPIX * (K / 2)) / 256, 256>>>(enc);       // 7
    final_kernel<<<1, 256>>>(out);                          // 8
}

// round 14
// speedup vs baseline: 1.3922x; 1.0085x over previous
#include <cuda_runtime.h>
#include <cuda_fp16.h>
#include <cstdint>

#define D      256
#define K      2048
#define BHW    4096
#define NPIX   65536
#define QELEMS 16777216
#define MARGIN 0.075f

// ---------------- device scratch ----------------
// A scratch (hi only): [pt 512][px 128][c 32 (^= px&7)] uint4
__device__ uint4 g_xA[(size_t)512 * 128 * 32];          // 32 MB
// B scratch (hi only): [slice 64][n 128][cl 8 (^= n&7)] uint4  (slice = kt*4+s)
__device__ uint4 g_xB[(size_t)64 * 128 * 8];            // 1 MB
__device__ float g_halfnorm[K];
__device__ int   g_idx[NPIX];
__device__ int   g_counts[K];
__device__ float g_loss;
__device__ int   g_ambig_cnt;
__device__ int   g_ambig[NPIX];
// per-half top2 results
__device__ float g_bestv[2 * NPIX];
__device__ float g_best2[2 * NPIX];
__device__ int   g_besti[2 * NPIX];

__device__ __forceinline__ void mma16(float* c, const uint32_t* a, const uint32_t* b) {
    asm volatile("mma.sync.aligned.m16n8k16.row.col.f32.f16.f16.f32 "
        "{%0,%1,%2,%3}, {%4,%5,%6,%7}, {%8,%9}, {%0,%1,%2,%3};"
        : "+f"(c[0]), "+f"(c[1]), "+f"(c[2]), "+f"(c[3])
        : "r"(a[0]), "r"(a[1]), "r"(a[2]), "r"(a[3]), "r"(b[0]), "r"(b[1]));
}
__device__ __forceinline__ void ldsm4(uint32_t* r, uint32_t addr) {
    asm volatile("ldmatrix.sync.aligned.m8n8.x4.shared.b16 {%0,%1,%2,%3}, [%4];"
        : "=r"(r[0]), "=r"(r[1]), "=r"(r[2]), "=r"(r[3]) : "r"(addr));
}
__device__ __forceinline__ uint32_t smem_u32(const void* p) {
    uint32_t a;
    asm("{ .reg .u64 t; cvta.to.shared.u64 t, %1; cvt.u32.u64 %0, t; }" : "=r"(a) : "l"(p));
    return a;
}
#define CPASYNC(dst, src) \
    asm volatile("cp.async.ca.shared.global [%0], [%1], 16;" :: "r"(dst), "l"(src))
#define CPCOMMIT() asm volatile("cp.async.commit_group;" ::: "memory")
#define CPWAIT0()  asm volatile("cp.async.wait_group 0;" ::: "memory")

__device__ __forceinline__ uint32_t packh2(float a, float b) {
    __half2 h2 = __halves2half2(__float2half_rn(a), __float2half_rn(b));
    return *reinterpret_cast<uint32_t*>(&h2);
}

// ---------------- kernel 0: halfnorm + zero counters ----------------
__global__ void prep_kernel(const float* __restrict__ emb) {
    int k = blockIdx.x * blockDim.x + threadIdx.x;
    if (k < K) {
        const float4* row = reinterpret_cast<const float4*>(emb + (size_t)k * D);
        float s = 0.f;
        #pragma unroll
        for (int i = 0; i < D / 4; i++) {
            float4 v = row[i];
            s += v.x * v.x + v.y * v.y + v.z * v.z + v.w * v.w;
        }
        g_halfnorm[k] = 0.5f * s;
        g_counts[k] = 0;
        if (k == 0) { g_loss = 0.f; g_ambig_cnt = 0; }
    }
}

// ---------------- kernel 1: -x -> fp16 hi, ldmatrix-ready A scratch ----------------
__global__ void split_x_kernel(const float* __restrict__ x) {
    __shared__ uint4 stg[64 * 32];   // [pxl][cs]
    int blk = blockIdx.x;
    int b = blk >> 6, pt = (blk >> 1) & 31, hpx = blk & 1;
    int tid = threadIdx.x;
    int hw0 = pt * 128 + hpx * 64;

    #pragma unroll
    for (int it = 0; it < 8; it++) {
        int id = tid + it * 256;
        int pxl = id & 63, c = id >> 6;
        float v[8];
        #pragma unroll
        for (int j = 0; j < 8; j++)
            v[j] = -x[((size_t)(b * 256 + c * 8 + j)) * 4096 + hw0 + pxl];
        uint4 hi;
        hi.x = packh2(v[0], v[1]); hi.y = packh2(v[2], v[3]);
        hi.z = packh2(v[4], v[5]); hi.w = packh2(v[6], v[7]);
        stg[pxl * 32 + (c ^ (pxl & 7))] = hi;
    }
    __syncthreads();
    size_t ob = (size_t)(blk >> 1) * 4096;
    #pragma unroll
    for (int it = 0; it < 8; it++) {
        int id = tid + it * 256;
        int pxl = id >> 5, cp = id & 31;
        g_xA[ob + (size_t)(hpx * 64 + pxl) * 32 + cp] = stg[pxl * 32 + cp];
    }
}

// ---------------- kernel 2: e -> fp16 hi, ldmatrix-ready B scratch ----------------
// layout: [slice = (n>>7)*4 + (d>>6)][n&127][cl = (d&63)/8, low3 ^= n&7]
__global__ void split_e_kernel(const float* __restrict__ emb) {
    __shared__ uint4 stg[64 * 32];   // [nl][s*8 + swz(cl)]
    int n0 = blockIdx.x * 64;
    int tid = threadIdx.x;
    #pragma unroll
    for (int it = 0; it < 8; it++) {
        int id = tid + it * 256;
        int c = id & 31, nl = id >> 5;
        float v[8];
        #pragma unroll
        for (int j = 0; j < 8; j++)
            v[j] = emb[(size_t)(n0 + nl) * D + c * 8 + j];
        uint4 hi;
        hi.x = packh2(v[0], v[1]); hi.y = packh2(v[2], v[3]);
        hi.z = packh2(v[4], v[5]); hi.w = packh2(v[6], v[7]);
        int s = c >> 3, cl = c & 7;
        stg[nl * 32 + s * 8 + (cl ^ (nl & 7))] = hi;
    }
    __syncthreads();
    int kt = n0 >> 7, nh = (n0 >> 6) & 1;
    #pragma unroll
    for (int it = 0; it < 8; it++) {
        int id = tid + it * 256;        // [s 4][nl 64][clp 8]
        int clp = id & 7, nl = (id >> 3) & 63, s = id >> 9;
        g_xB[((size_t)(kt * 4 + s) * 128 + nh * 64 + nl) * 8 + clp] =
            stg[nl * 32 + s * 8 + clp];
    }
}

// ---------------- kernel 3: fp16-hi screening GEMM, K-split, 2 CTA/SM ----------------
// smem bytes: A[128][32]u4 @0 (64K) | B[2][128][8]u4 @64K (32K) | hn @96K+2K (4K)
//             srv @102400 (1K) | sr2 @103424 (1K) | sri @104448 (1K) => 105472
#define BOFF   65536
#define BUFSZ  16384
#define HNB    98304
#define SRVB   102400
#define SR2B   103424
#define SRIB   104448
#define SMEM_BYTES 105472

__global__ __launch_bounds__(256, 2) void argmin_fp16_kernel() {
    extern __shared__ uint4 sm4[];
    uint32_t sb = smem_u32(sm4);
    char* smc = reinterpret_cast<char*>(sm4);
    float* hnsm = reinterpret_cast<float*>(smc + HNB);
    float* srv  = reinterpret_cast<float*>(smc + SRVB);
    float* sr2  = reinterpret_cast<float*>(smc + SR2B);
    int*   sri  = reinterpret_cast<int*>(smc + SRIB);

    int tid = threadIdx.x;
    int w = tid >> 5, lane = tid & 31;
    int warpM = w >> 1, warpN = w & 1;        // 4 x 2 warps; tile 32px x 64n
    int g = lane >> 2, tig = lane & 3;
    int khalf = blockIdx.x & 1, pt = blockIdx.x >> 1;

    srv[tid] = 3.4e38f; sr2[tid] = 3.4e38f; sri[tid] = 0;

    // prologue: A resident (16/thread) + B step0 (4/thread)
    {
        const uint4* asrc = &g_xA[(size_t)pt * 4096];
        #pragma unroll
        for (int i = 0; i < 16; i++) {
            int id = tid + i * 256;
            CPASYNC(sb + id * 16, asrc + id);
        }
        const uint4* bsrc = &g_xB[(size_t)khalf * 32768];
        #pragma unroll
        for (int i = 0; i < 4; i++) {
            int id = tid + i * 256;
            CPASYNC(sb + BOFF + id * 16, bsrc + id);
        }
        CPCOMMIT();
        // halfnorm preload for this half
        #pragma unroll
        for (int i = 0; i < 4; i++)
            hnsm[tid + i * 256] = g_halfnorm[khalf * 1024 + tid + i * 256];
        CPWAIT0();
    }

    int pxA0 = warpM * 32 + (lane & 15);
    int kcA  = lane >> 4;
    int nB0  = warpN * 64 + (lane & 7) + ((lane >> 4) << 3);
    int kcB  = (lane >> 3) & 1;

    float acc[2][8][4];

    for (int nt = 0; nt < 8; nt++) {
        #pragma unroll
        for (int mf = 0; mf < 2; mf++)
            #pragma unroll
            for (int nf = 0; nf < 8; nf++)
                #pragma unroll
                for (int i = 0; i < 4; i++) acc[mf][nf][i] = 0.f;

        for (int s = 0; s < 4; s++) {          // 64-d slices
            int step = nt * 4 + s;
            int buf = step & 1;
            __syncthreads();
            if (step < 31) {
                const uint4* bsrc = &g_xB[((size_t)khalf * 32 + step + 1) * 1024];
                uint32_t bdst = sb + BOFF + (buf ^ 1) * BUFSZ;
                #pragma unroll
                for (int i = 0; i < 4; i++) {
                    int id = tid + i * 256;
                    CPASYNC(bdst + id * 16, bsrc + id);
                }
                CPCOMMIT();
            }
            uint32_t bbase = sb + BOFF + buf * BUFSZ;
            #pragma unroll
            for (int kb = 0; kb < 4; kb++) {
                int cA = s * 8 + kb * 2 + kcA;
                uint32_t ah[2][4];
                #pragma unroll
                for (int mf = 0; mf < 2; mf++) {
                    int px = pxA0 + mf * 16;
                    uint32_t ro = (uint32_t)(px * 32 + (cA ^ (px & 7))) * 16;
                    ldsm4(ah[mf], sb + ro);
                }
                int clB = kb * 2 + kcB;
                uint32_t bh[4][4];
                #pragma unroll
                for (int p = 0; p < 4; p++) {
                    int n = nB0 + p * 16;
                    uint32_t ro = (uint32_t)(n * 8 + (clB ^ (n & 7))) * 16;
                    ldsm4(bh[p], bbase + ro);
                }
                #pragma unroll
                for (int mf = 0; mf < 2; mf++)
                    #pragma unroll
                    for (int nf = 0; nf < 8; nf++)
                        mma16(acc[mf][nf], ah[mf], &bh[nf >> 1][(nf & 1) * 2]);
            }
            CPWAIT0();
        }
        // epilogue: add halfnorm (from smem), per-pixel top-2 fold
        float hn[8][2];
        int clocal = nt * 128 + warpN * 64 + tig * 2;     // 0..1023 within half
        #pragma unroll
        for (int nf = 0; nf < 8; nf++) {
            hn[nf][0] = hnsm[clocal + nf * 8];
            hn[nf][1] = hnsm[clocal + nf * 8 + 1];
        }
        #pragma unroll
        for (int mf = 0; mf < 2; mf++) {
            #pragma unroll
            for (int half = 0; half < 2; half++) {
                float v = 3.4e38f, v2 = 3.4e38f; int vi = 0;
                #pragma unroll
                for (int nf = 0; nf < 8; nf++) {
                    #pragma unroll
                    for (int c = 0; c < 2; c++) {
                        float sc = acc[mf][nf][half * 2 + c] + hn[nf][c];
                        int ci = khalf * 1024 + clocal + nf * 8 + c;
                        if (sc < v) { v2 = v; v = sc; vi = ci; }
                        else if (sc < v2) { v2 = sc; }
                    }
                }
                #pragma unroll
                for (int o = 1; o <= 2; o <<= 1) {
                    float ov  = __shfl_xor_sync(0xffffffffu, v, o);
                    int   oi  = __shfl_xor_sync(0xffffffffu, vi, o);
                    float ov2 = __shfl_xor_sync(0xffffffffu, v2, o);
                    float nv2 = fminf(fmaxf(v, ov), fminf(v2, ov2));
                    bool take = (ov < v) || (ov == v && oi < vi);
                    if (take) { v = ov; vi = oi; }
                    v2 = nv2;
                }
                if (tig == 0) {
                    int row = warpM * 32 + mf * 16 + half * 8 + g;
                    int slot = row * 2 + warpN;
                    float sv = srv[slot], sv2 = sr2[slot]; int si = sri[slot];
                    float nv2 = fminf(fmaxf(v, sv), fminf(v2, sv2));
                    bool take = (v < sv) || (v == sv && vi < si);
                    srv[slot] = take ? v : sv;
                    sri[slot] = take ? vi : si;
                    sr2[slot] = nv2;
                }
            }
        }
    }
    __syncthreads();
    if (tid < 128) {
        float v = srv[tid * 2], v2 = sr2[tid * 2]; int vi = sri[tid * 2];
        {
            float ov = srv[tid * 2 + 1], ov2 = sr2[tid * 2 + 1];
            int oi = sri[tid * 2 + 1];
            float nv2 = fminf(fmaxf(v, ov), fminf(v2, ov2));
            bool take = (ov < v) || (ov == v && oi < vi);
            if (take) { v = ov; vi = oi; }
            v2 = nv2;
        }
        int n = pt * 128 + tid;
        g_bestv[khalf * NPIX + n] = v;
        g_best2[khalf * NPIX + n] = v2;
        g_besti[khalf * NPIX + n] = vi;
    }
}

// ---------------- kernel 4: merge halves -> idx, counts, ambig list ----------------
__global__ void merge_kernel() {
    int n = blockIdx.x * 256 + threadIdx.x;
    float v0 = g_bestv[n],        v1 = g_bestv[NPIX + n];
    float w0 = g_best2[n],        w1 = g_best2[NPIX + n];
    int   i0 = g_besti[n],        i1 = g_besti[NPIX + n];
    bool t1 = v1 < v0;                        // tie -> half0 (lower indices)
    float v  = t1 ? v1 : v0;
    int   vi = t1 ? i1 : i0;
    float v2 = fminf(t1 ? v0 : v1, t1 ? w1 : w0);
    g_idx[n] = vi;
    atomicAdd(&g_counts[vi], 1);
    if (v2 - v < MARGIN) {
        int pos = atomicAdd(&g_ambig_cnt, 1);
        g_ambig[pos] = n;
    }
}

// ---------------- kernel 5: exact fp32 brute force (coalesced, 16 px / pass) ----------------
#define BPX 16
__global__ __launch_bounds__(256, 2) void brute_kernel(const float* __restrict__ x,
                                                       const float* __restrict__ emb) {
    __shared__ float sx[BPX][256];
    __shared__ float wv[BPX][8];
    __shared__ int   wi[BPX][8];
    int tid = threadIdx.x;
    int lane = tid & 31, wrp = tid >> 5;
    int seg = tid & 7, kg = tid >> 3;
    int count = g_ambig_cnt;

    for (int base = blockIdx.x * BPX; base < count; base += gridDim.x * BPX) {
        __syncthreads();
        for (int i = tid; i < BPX * 256; i += 256) {
            int px = i >> 8, d = i & 255;
            int li = base + px;
            int n = g_ambig[li < count ? li : count - 1];
            sx[px][d] = x[(((size_t)(n >> 12) * 256 + d) << 12) | (uint32_t)(n & 4095)];
        }
        __syncthreads();
        float best[BPX]; int bik[BPX];
        #pragma unroll
        for (int p = 0; p < BPX; p++) { best[p] = 3.4e38f; bik[p] = 0; }

        for (int kt = 0; kt < 64; kt++) {
            int k = kt * 32 + kg;
            const float4* er = reinterpret_cast<const float4*>(emb + (size_t)k * 256);
            float4 e[8];
            #pragma unroll
            for (int c = 0; c < 8; c++) e[c] = er[c * 8 + seg];
            float hn = g_halfnorm[k];
            #pragma unroll
            for (int p = 0; p < BPX; p++) {
                float dot = 0.f;
                #pragma unroll
                for (int c = 0; c < 8; c++) {
                    const float* xs = &sx[p][c * 32 + seg * 4];
                    dot = fmaf(xs[0], e[c].x, dot);
                    dot = fmaf(xs[1], e[c].y, dot);
                    dot = fmaf(xs[2], e[c].z, dot);
                    dot = fmaf(xs[3], e[c].w, dot);
                }
                dot += __shfl_xor_sync(0xffffffffu, dot, 1);
                dot += __shfl_xor_sync(0xffffffffu, dot, 2);
                dot += __shfl_xor_sync(0xffffffffu, dot, 4);
                float sc = hn - dot;
                if (sc < best[p]) { best[p] = sc; bik[p] = k; }
            }
        }
        #pragma unroll
        for (int p = 0; p < BPX; p++) {
            float v = best[p]; int vi = bik[p];
            #pragma unroll
            for (int o = 8; o <= 16; o <<= 1) {
                float ov = __shfl_xor_sync(0xffffffffu, v, o);
                int   oi = __shfl_xor_sync(0xffffffffu, vi, o);
                if (ov < v || (ov == v && oi < vi)) { v = ov; vi = oi; }
            }
            if (lane == 0) { wv[p][wrp] = v; wi[p][wrp] = vi; }
        }
        __syncthreads();
        if (tid < BPX * 8) {
            int p = tid >> 3, wq = tid & 7;
            float v = wv[p][wq]; int vi = wi[p][wq];
            #pragma unroll
            for (int o = 1; o < 8; o <<= 1) {
                float ov = __shfl_xor_sync(0xffffffffu, v, o);
                int   oi = __shfl_xor_sync(0xffffffffu, vi, o);
                if (ov < v || (ov == v && oi < vi)) { v = ov; vi = oi; }
            }
            if (wq == 0) {
                int li = base + p;
                if (li < count) {
                    int n = g_ambig[li];
                    int old = g_idx[n];
                    if (old != vi) {
                        g_idx[n] = vi;
                        atomicAdd(&g_counts[old], -1);
                        atomicAdd(&g_counts[vi], 1);
                    }
                }
            }
        }
    }
}

// ---------------- kernel 6: transposed coalesced gather + loss ----------------
__global__ __launch_bounds__(256) void quantize_kernel(const float* __restrict__ x,
                                                       const float* __restrict__ emb,
                                                       float* __restrict__ outq) {
    __shared__ float sq[32 * 257];
    __shared__ int   sk[32];
    __shared__ float ls[8];
    int tid = threadIdx.x;
    int n0 = blockIdx.x * 32;
    int b = n0 >> 12, hw0 = n0 & 4095;
    if (tid < 32) sk[tid] = g_idx[n0 + tid];
    __syncthreads();
    #pragma unroll 8
    for (int j = 0; j < 32; j++) {
        sq[j * 257 + tid] = __ldg(emb + (size_t)sk[j] * 256 + tid);
    }
    __syncthreads();
    float l = 0.f;
    int dr = tid >> 5, px = tid & 31;
    #pragma unroll 8
    for (int j = 0; j < 32; j++) {
        int d = j * 8 + dr;
        size_t o = ((size_t)(b * 256 + d)) * 4096 + hw0 + px;
        float q = sq[px * 257 + d];
        float xv = x[o];
        __stcs(outq + o, q);
        float diff = q - xv;
        l += diff * diff;
    }
    #pragma unroll
    for (int off = 16; off; off >>= 1) l += __shfl_xor_sync(0xffffffffu, l, off);
    int lane = tid & 31, wq = tid >> 5;
    if (lane == 0) ls[wq] = l;
    __syncthreads();
    if (tid == 0) {
        float ssum = 0.f;
        #pragma unroll
        for (int i = 0; i < 8; i++) ssum += ls[i];
        atomicAdd(&g_loss, ssum);
    }
}

// ---------------- kernel 7: one-hot encodings ----------------
__global__ void enc_kernel(float2* __restrict__ enc) {
    int i2 = blockIdx.x * 256 + threadIdx.x;
    int n = i2 >> 10;
    int j = (i2 & 1023) << 1;
    int k = g_idx[n];
    float2 v;
    v.x = (j == k)     ? 1.f : 0.f;
    v.y = (j + 1 == k) ? 1.f : 0.f;
    __stcs(enc + i2, v);
}

// ---------------- kernel 8: scalars ----------------
__global__ void final_kernel(float* __restrict__ out) {
    __shared__ float sh[256];
    int t = threadIdx.x;
    float s = 0.f;
    for (int k = t; k < K; k += 256) {
        float p = (float)g_counts[k] * (1.0f / (float)NPIX);
        s += p * logf(p + 1e-10f);
    }
    sh[t] = s;
    __syncthreads();
    for (int o = 128; o; o >>= 1) {
        if (t < o) sh[t] += sh[t + o];
        __syncthreads();
    }
    if (t == 0) {
        out[0] = 0.25f * g_loss / (float)QELEMS;
        out[1 + QELEMS] = expf(-sh[0]);
    }
}

extern "C" void kernel_launch(void* const* d_in, const int* in_sizes, int n_in,
                              void* d_out, int out_size) {
    const float* x   = (const float*)d_in[0];
    const float* emb = (const float*)d_in[1];
    float* out  = (float*)d_out;
    float* outq = out + 1;
    float2* enc = (float2*)(out + 2 + QELEMS);

    cudaFuncSetAttribute(argmin_fp16_kernel, cudaFuncAttributeMaxDynamicSharedMemorySize,
                         SMEM_BYTES);

    prep_kernel<<<8, 256>>>(emb);                           // 0
    split_x_kernel<<<1024, 256>>>(x);                       // 1
    split_e_kernel<<<32, 256>>>(emb);                       // 2
    argmin_fp16_kernel<<<1024, 256, SMEM_BYTES>>>();        // 3 (profiled slot)
    merge_kernel<<<NPIX / 256, 256>>>();                    // 4
    brute_kernel<<<148, 256>>>(x, emb);                     // 5
    quantize_kernel<<<NPIX / 32, 256>>>(x, emb, outq);      // 6
    enc_kernel<<<(NPIX * (K / 2)) / 256, 256>>>(enc);       // 7
    final_kernel<<<1, 256>>>(out);                          // 8
}

// round 15
// speedup vs baseline: 1.8851x; 1.3541x over previous
#include <cuda_runtime.h>
#include <cuda_fp16.h>
#include <cstdint>

#define D      256
#define K      2048
#define BHW    4096
#define NPIX   65536
#define QELEMS 16777216
#define MARGIN 0.075f

// ---------------- device scratch ----------------
// A scratch (hi only): [pt 512][px 128][c 32 (^= px&7)] uint4
__device__ uint4 g_xA[(size_t)512 * 128 * 32];          // 32 MB
// B scratch (hi only): [slice 64][n 128][cl 8 (^= n&7)] uint4  (slice = kt*4+s)
__device__ uint4 g_xB[(size_t)64 * 128 * 8];            // 1 MB
__device__ float g_halfnorm[K];
__device__ int   g_idx[NPIX];
__device__ int   g_counts[K];
__device__ float g_loss;
__device__ int   g_ambig_cnt;
__device__ int   g_ambig[NPIX];
__device__ unsigned long long g_bmin[NPIX];   // packed (sortable score, idx) minima
// per-half top2 results
__device__ float g_bestv[2 * NPIX];
__device__ float g_best2[2 * NPIX];
__device__ int   g_besti[2 * NPIX];

__device__ __forceinline__ void mma16(float* c, const uint32_t* a, const uint32_t* b) {
    asm volatile("mma.sync.aligned.m16n8k16.row.col.f32.f16.f16.f32 "
        "{%0,%1,%2,%3}, {%4,%5,%6,%7}, {%8,%9}, {%0,%1,%2,%3};"
        : "+f"(c[0]), "+f"(c[1]), "+f"(c[2]), "+f"(c[3])
        : "r"(a[0]), "r"(a[1]), "r"(a[2]), "r"(a[3]), "r"(b[0]), "r"(b[1]));
}
__device__ __forceinline__ void ldsm4(uint32_t* r, uint32_t addr) {
    asm volatile("ldmatrix.sync.aligned.m8n8.x4.shared.b16 {%0,%1,%2,%3}, [%4];"
        : "=r"(r[0]), "=r"(r[1]), "=r"(r[2]), "=r"(r[3]) : "r"(addr));
}
__device__ __forceinline__ uint32_t smem_u32(const void* p) {
    uint32_t a;
    asm("{ .reg .u64 t; cvta.to.shared.u64 t, %1; cvt.u32.u64 %0, t; }" : "=r"(a) : "l"(p));
    return a;
}
#define CPASYNC(dst, src) \
    asm volatile("cp.async.ca.shared.global [%0], [%1], 16;" :: "r"(dst), "l"(src))
#define CPCOMMIT() asm volatile("cp.async.commit_group;" ::: "memory")
#define CPWAIT0()  asm volatile("cp.async.wait_group 0;" ::: "memory")

__device__ __forceinline__ uint32_t packh2(float a, float b) {
    __half2 h2 = __halves2half2(__float2half_rn(a), __float2half_rn(b));
    return *reinterpret_cast<uint32_t*>(&h2);
}
// float -> order-preserving uint32
__device__ __forceinline__ uint32_t fkey(float f) {
    uint32_t u = __float_as_uint(f);
    return u ^ (((int)u >> 31) | 0x80000000u);
}

// ---------------- kernel 0: halfnorm + zero counters ----------------
__global__ void prep_kernel(const float* __restrict__ emb) {
    int k = blockIdx.x * blockDim.x + threadIdx.x;
    if (k < K) {
        const float4* row = reinterpret_cast<const float4*>(emb + (size_t)k * D);
        float s = 0.f;
        #pragma unroll
        for (int i = 0; i < D / 4; i++) {
            float4 v = row[i];
            s += v.x * v.x + v.y * v.y + v.z * v.z + v.w * v.w;
        }
        g_halfnorm[k] = 0.5f * s;
        g_counts[k] = 0;
        if (k == 0) { g_loss = 0.f; g_ambig_cnt = 0; }
    }
}

// ---------------- kernel 1: -x -> fp16 hi, ldmatrix-ready A scratch ----------------
__global__ void split_x_kernel(const float* __restrict__ x) {
    __shared__ uint4 stg[64 * 32];   // [pxl][cs]
    int blk = blockIdx.x;
    int b = blk >> 6, pt = (blk >> 1) & 31, hpx = blk & 1;
    int tid = threadIdx.x;
    int hw0 = pt * 128 + hpx * 64;

    #pragma unroll
    for (int it = 0; it < 8; it++) {
        int id = tid + it * 256;
        int pxl = id & 63, c = id >> 6;
        float v[8];
        #pragma unroll
        for (int j = 0; j < 8; j++)
            v[j] = -x[((size_t)(b * 256 + c * 8 + j)) * 4096 + hw0 + pxl];
        uint4 hi;
        hi.x = packh2(v[0], v[1]); hi.y = packh2(v[2], v[3]);
        hi.z = packh2(v[4], v[5]); hi.w = packh2(v[6], v[7]);
        stg[pxl * 32 + (c ^ (pxl & 7))] = hi;
    }
    __syncthreads();
    size_t ob = (size_t)(blk >> 1) * 4096;
    #pragma unroll
    for (int it = 0; it < 8; it++) {
        int id = tid + it * 256;
        int pxl = id >> 5, cp = id & 31;
        g_xA[ob + (size_t)(hpx * 64 + pxl) * 32 + cp] = stg[pxl * 32 + cp];
    }
}

// ---------------- kernel 2: e -> fp16 hi, ldmatrix-ready B scratch ----------------
__global__ void split_e_kernel(const float* __restrict__ emb) {
    __shared__ uint4 stg[64 * 32];   // [nl][s*8 + swz(cl)]
    int n0 = blockIdx.x * 64;
    int tid = threadIdx.x;
    #pragma unroll
    for (int it = 0; it < 8; it++) {
        int id = tid + it * 256;
        int c = id & 31, nl = id >> 5;
        float v[8];
        #pragma unroll
        for (int j = 0; j < 8; j++)
            v[j] = emb[(size_t)(n0 + nl) * D + c * 8 + j];
        uint4 hi;
        hi.x = packh2(v[0], v[1]); hi.y = packh2(v[2], v[3]);
        hi.z = packh2(v[4], v[5]); hi.w = packh2(v[6], v[7]);
        int s = c >> 3, cl = c & 7;
        stg[nl * 32 + s * 8 + (cl ^ (nl & 7))] = hi;
    }
    __syncthreads();
    int kt = n0 >> 7, nh = (n0 >> 6) & 1;
    #pragma unroll
    for (int it = 0; it < 8; it++) {
        int id = tid + it * 256;        // [s 4][nl 64][clp 8]
        int clp = id & 7, nl = (id >> 3) & 63, s = id >> 9;
        g_xB[((size_t)(kt * 4 + s) * 128 + nh * 64 + nl) * 8 + clp] =
            stg[nl * 32 + s * 8 + clp];
    }
}

// ---------------- kernel 3: fp16-hi screening GEMM, K-split, 2 CTA/SM ----------------
#define BOFF   65536
#define BUFSZ  16384
#define HNB    98304
#define SRVB   102400
#define SR2B   103424
#define SRIB   104448
#define SMEM_BYTES 105472

__global__ __launch_bounds__(256, 2) void argmin_fp16_kernel() {
    extern __shared__ uint4 sm4[];
    uint32_t sb = smem_u32(sm4);
    char* smc = reinterpret_cast<char*>(sm4);
    float* hnsm = reinterpret_cast<float*>(smc + HNB);
    float* srv  = reinterpret_cast<float*>(smc + SRVB);
    float* sr2  = reinterpret_cast<float*>(smc + SR2B);
    int*   sri  = reinterpret_cast<int*>(smc + SRIB);

    int tid = threadIdx.x;
    int w = tid >> 5, lane = tid & 31;
    int warpM = w >> 1, warpN = w & 1;        // 4 x 2 warps; tile 32px x 64n
    int g = lane >> 2, tig = lane & 3;
    int khalf = blockIdx.x & 1, pt = blockIdx.x >> 1;

    srv[tid] = 3.4e38f; sr2[tid] = 3.4e38f; sri[tid] = 0;

    // prologue: A resident (16/thread) + B step0 (4/thread)
    {
        const uint4* asrc = &g_xA[(size_t)pt * 4096];
        #pragma unroll
        for (int i = 0; i < 16; i++) {
            int id = tid + i * 256;
            CPASYNC(sb + id * 16, asrc + id);
        }
        const uint4* bsrc = &g_xB[(size_t)khalf * 32768];
        #pragma unroll
        for (int i = 0; i < 4; i++) {
            int id = tid + i * 256;
            CPASYNC(sb + BOFF + id * 16, bsrc + id);
        }
        CPCOMMIT();
        #pragma unroll
        for (int i = 0; i < 4; i++)
            hnsm[tid + i * 256] = g_halfnorm[khalf * 1024 + tid + i * 256];
        CPWAIT0();
    }

    int pxA0 = warpM * 32 + (lane & 15);
    int kcA  = lane >> 4;
    int nB0  = warpN * 64 + (lane & 7) + ((lane >> 4) << 3);
    int kcB  = (lane >> 3) & 1;

    float acc[2][8][4];

    for (int nt = 0; nt < 8; nt++) {
        #pragma unroll
        for (int mf = 0; mf < 2; mf++)
            #pragma unroll
            for (int nf = 0; nf < 8; nf++)
                #pragma unroll
                for (int i = 0; i < 4; i++) acc[mf][nf][i] = 0.f;

        for (int s = 0; s < 4; s++) {          // 64-d slices
            int step = nt * 4 + s;
            int buf = step & 1;
            __syncthreads();
            if (step < 31) {
                const uint4* bsrc = &g_xB[((size_t)khalf * 32 + step + 1) * 1024];
                uint32_t bdst = sb + BOFF + (buf ^ 1) * BUFSZ;
                #pragma unroll
                for (int i = 0; i < 4; i++) {
                    int id = tid + i * 256;
                    CPASYNC(bdst + id * 16, bsrc + id);
                }
                CPCOMMIT();
            }
            uint32_t bbase = sb + BOFF + buf * BUFSZ;
            #pragma unroll
            for (int kb = 0; kb < 4; kb++) {
                int cA = s * 8 + kb * 2 + kcA;
                uint32_t ah[2][4];
                #pragma unroll
                for (int mf = 0; mf < 2; mf++) {
                    int px = pxA0 + mf * 16;
                    uint32_t ro = (uint32_t)(px * 32 + (cA ^ (px & 7))) * 16;
                    ldsm4(ah[mf], sb + ro);
                }
                int clB = kb * 2 + kcB;
                uint32_t bh[4][4];
                #pragma unroll
                for (int p = 0; p < 4; p++) {
                    int n = nB0 + p * 16;
                    uint32_t ro = (uint32_t)(n * 8 + (clB ^ (n & 7))) * 16;
                    ldsm4(bh[p], bbase + ro);
                }
                #pragma unroll
                for (int mf = 0; mf < 2; mf++)
                    #pragma unroll
                    for (int nf = 0; nf < 8; nf++)
                        mma16(acc[mf][nf], ah[mf], &bh[nf >> 1][(nf & 1) * 2]);
            }
            CPWAIT0();
        }
        // epilogue: add halfnorm (from smem), per-pixel top-2 fold
        float hn[8][2];
        int clocal = nt * 128 + warpN * 64 + tig * 2;
        #pragma unroll
        for (int nf = 0; nf < 8; nf++) {
            hn[nf][0] = hnsm[clocal + nf * 8];
            hn[nf][1] = hnsm[clocal + nf * 8 + 1];
        }
        #pragma unroll
        for (int mf = 0; mf < 2; mf++) {
            #pragma unroll
            for (int half = 0; half < 2; half++) {
                float v = 3.4e38f, v2 = 3.4e38f; int vi = 0;
                #pragma unroll
                for (int nf = 0; nf < 8; nf++) {
                    #pragma unroll
                    for (int c = 0; c < 2; c++) {
                        float sc = acc[mf][nf][half * 2 + c] + hn[nf][c];
                        int ci = khalf * 1024 + clocal + nf * 8 + c;
                        if (sc < v) { v2 = v; v = sc; vi = ci; }
                        else if (sc < v2) { v2 = sc; }
                    }
                }
                #pragma unroll
                for (int o = 1; o <= 2; o <<= 1) {
                    float ov  = __shfl_xor_sync(0xffffffffu, v, o);
                    int   oi  = __shfl_xor_sync(0xffffffffu, vi, o);
                    float ov2 = __shfl_xor_sync(0xffffffffu, v2, o);
                    float nv2 = fminf(fmaxf(v, ov), fminf(v2, ov2));
                    bool take = (ov < v) || (ov == v && oi < vi);
                    if (take) { v = ov; vi = oi; }
                    v2 = nv2;
                }
                if (tig == 0) {
                    int row = warpM * 32 + mf * 16 + half * 8 + g;
                    int slot = row * 2 + warpN;
                    float sv = srv[slot], sv2 = sr2[slot]; int si = sri[slot];
                    float nv2 = fminf(fmaxf(v, sv), fminf(v2, sv2));
                    bool take = (v < sv) || (v == sv && vi < si);
                    srv[slot] = take ? v : sv;
                    sri[slot] = take ? vi : si;
                    sr2[slot] = nv2;
                }
            }
        }
    }
    __syncthreads();
    if (tid < 128) {
        float v = srv[tid * 2], v2 = sr2[tid * 2]; int vi = sri[tid * 2];
        {
            float ov = srv[tid * 2 + 1], ov2 = sr2[tid * 2 + 1];
            int oi = sri[tid * 2 + 1];
            float nv2 = fminf(fmaxf(v, ov), fminf(v2, ov2));
            bool take = (ov < v) || (ov == v && oi < vi);
            if (take) { v = ov; vi = oi; }
            v2 = nv2;
        }
        int n = pt * 128 + tid;
        g_bestv[khalf * NPIX + n] = v;
        g_best2[khalf * NPIX + n] = v2;
        g_besti[khalf * NPIX + n] = vi;
    }
}

// ---------------- kernel 4: merge halves -> idx, counts, ambig list ----------------
__global__ void merge_kernel() {
    int n = blockIdx.x * 256 + threadIdx.x;
    float v0 = g_bestv[n],        v1 = g_bestv[NPIX + n];
    float w0 = g_best2[n],        w1 = g_best2[NPIX + n];
    int   i0 = g_besti[n],        i1 = g_besti[NPIX + n];
    bool t1 = v1 < v0;
    float v  = t1 ? v1 : v0;
    int   vi = t1 ? i1 : i0;
    float v2 = fminf(t1 ? v0 : v1, t1 ? w1 : w0);
    g_idx[n] = vi;
    atomicAdd(&g_counts[vi], 1);
    if (v2 - v < MARGIN) {
        int pos = atomicAdd(&g_ambig_cnt, 1);
        g_ambig[pos] = n;
        g_bmin[n] = 0xFFFFFFFFFFFFFFFFULL;
    }
}

// ---------------- kernel 5: exact fp32 brute, (16px, 256-code) units ----------------
#define BPX 16
__global__ __launch_bounds__(256, 2) void brute_kernel(const float* __restrict__ x,
                                                       const float* __restrict__ emb) {
    __shared__ float sx[BPX][256];
    int tid = threadIdx.x;
    int lane = tid & 31, wrp = tid >> 5;
    int seg = tid & 7, kg = (tid >> 3) & 31;    // within-chunk k group (32 per chunk)
    int count = g_ambig_cnt;
    int ngroups = (count + BPX - 1) / BPX;
    int nunits = ngroups * 8;

    for (int u = blockIdx.x; u < nunits; u += gridDim.x) {
        int grp = u >> 3, kc = u & 7;           // 256-code chunk kc
        int base = grp * BPX;
        __syncthreads();
        for (int i = tid; i < BPX * 256; i += 256) {
            int px = i >> 8, d = i & 255;
            int li = base + px;
            int n = g_ambig[li < count ? li : count - 1];
            sx[px][d] = x[(((size_t)(n >> 12) * 256 + d) << 12) | (uint32_t)(n & 4095)];
        }
        __syncthreads();
        float best[BPX]; int bik[BPX];
        #pragma unroll
        for (int p = 0; p < BPX; p++) { best[p] = 3.4e38f; bik[p] = 0; }

        for (int kt = 0; kt < 8; kt++) {
            int k = kc * 256 + kt * 32 + kg;
            const float4* er = reinterpret_cast<const float4*>(emb + (size_t)k * 256);
            float4 e[8];
            #pragma unroll
            for (int c = 0; c < 8; c++) e[c] = er[c * 8 + seg];
            float hn = g_halfnorm[k];
            #pragma unroll
            for (int p = 0; p < BPX; p++) {
                float dot = 0.f;
                #pragma unroll
                for (int c = 0; c < 8; c++) {
                    const float* xs = &sx[p][c * 32 + seg * 4];
                    dot = fmaf(xs[0], e[c].x, dot);
                    dot = fmaf(xs[1], e[c].y, dot);
                    dot = fmaf(xs[2], e[c].z, dot);
                    dot = fmaf(xs[3], e[c].w, dot);
                }
                dot += __shfl_xor_sync(0xffffffffu, dot, 1);
                dot += __shfl_xor_sync(0xffffffffu, dot, 2);
                dot += __shfl_xor_sync(0xffffffffu, dot, 4);
                float sc = hn - dot;
                if (sc < best[p]) { best[p] = sc; bik[p] = k; }
            }
        }
        // per-warp fold (lanes 8,16 apart differ in kg), then atomicMin
        #pragma unroll
        for (int p = 0; p < BPX; p++) {
            float v = best[p]; int vi = bik[p];
            #pragma unroll
            for (int o = 8; o <= 16; o <<= 1) {
                float ov = __shfl_xor_sync(0xffffffffu, v, o);
                int   oi = __shfl_xor_sync(0xffffffffu, vi, o);
                if (ov < v || (ov == v && oi < vi)) { v = ov; vi = oi; }
            }
            if (lane == 0) {
                int li = base + p;
                if (li < count) {
                    unsigned long long key =
                        ((unsigned long long)fkey(v) << 32) | (unsigned)vi;
                    atomicMin(&g_bmin[g_ambig[li]], key);
                }
            }
        }
    }
}

// ---------------- kernel 6: apply brute results ----------------
__global__ void fix_kernel() {
    int count = g_ambig_cnt;
    for (int i = blockIdx.x * 256 + threadIdx.x; i < count; i += gridDim.x * 256) {
        int n = g_ambig[i];
        int vi = (int)(g_bmin[n] & 0xFFFFFFFFu);
        int old = g_idx[n];
        if (old != vi) {
            g_idx[n] = vi;
            atomicAdd(&g_counts[old], -1);
            atomicAdd(&g_counts[vi], 1);
        }
    }
}

// ---------------- kernel 7: transposed coalesced gather + loss ----------------
__global__ __launch_bounds__(256) void quantize_kernel(const float* __restrict__ x,
                                                       const float* __restrict__ emb,
                                                       float* __restrict__ outq) {
    __shared__ float sq[32 * 257];
    __shared__ int   sk[32];
    __shared__ float ls[8];
    int tid = threadIdx.x;
    int n0 = blockIdx.x * 32;
    int b = n0 >> 12, hw0 = n0 & 4095;
    if (tid < 32) sk[tid] = g_idx[n0 + tid];
    __syncthreads();
    #pragma unroll 8
    for (int j = 0; j < 32; j++) {
        sq[j * 257 + tid] = __ldg(emb + (size_t)sk[j] * 256 + tid);
    }
    __syncthreads();
    float l = 0.f;
    int dr = tid >> 5, px = tid & 31;
    #pragma unroll 8
    for (int j = 0; j < 32; j++) {
        int d = j * 8 + dr;
        size_t o = ((size_t)(b * 256 + d)) * 4096 + hw0 + px;
        float q = sq[px * 257 + d];
        float xv = x[o];
        __stcs(outq + o, q);
        float diff = q - xv;
        l += diff * diff;
    }
    #pragma unroll
    for (int off = 16; off; off >>= 1) l += __shfl_xor_sync(0xffffffffu, l, off);
    int lane = tid & 31, wq = tid >> 5;
    if (lane == 0) ls[wq] = l;
    __syncthreads();
    if (tid == 0) {
        float ssum = 0.f;
        #pragma unroll
        for (int i = 0; i < 8; i++) ssum += ls[i];
        atomicAdd(&g_loss, ssum);
    }
}

// ---------------- kernel 8: one-hot encodings, float4 stores ----------------
// base = out + 2 + QELEMS (8B aligned); base+2 floats is 16B aligned.
__global__ void enc_kernel(float* __restrict__ base) {
    size_t i4 = (size_t)blockIdx.x * 256 + threadIdx.x;   // 0..33554431
    const size_t LAST = ((size_t)NPIX * K - 2) / 4;       // 33554431 (tail unit)
    if (i4 == 0) {
        int k = g_idx[0];
        __stcs(base + 0, (0 == k) ? 1.f : 0.f);
        __stcs(base + 1, (1 == k) ? 1.f : 0.f);
    }
    if (i4 >= LAST) {
        if (i4 == LAST) {
            int k = g_idx[NPIX - 1];
            __stcs(base + (size_t)NPIX * K - 2, (K - 2 == k) ? 1.f : 0.f);
            __stcs(base + (size_t)NPIX * K - 1, (K - 1 == k) ? 1.f : 0.f);
        }
        return;
    }
    size_t e0 = i4 * 4 + 2;
    int n = (int)(e0 >> 11), j = (int)(e0 & 2047);
    int k = g_idx[n];
    float4 v;
    if (j != 2046) {
        v.x = (j     == k) ? 1.f : 0.f;
        v.y = (j + 1 == k) ? 1.f : 0.f;
        v.z = (j + 2 == k) ? 1.f : 0.f;
        v.w = (j + 3 == k) ? 1.f : 0.f;
    } else {
        int k2 = g_idx[n + 1];
        v.x = (2046 == k)  ? 1.f : 0.f;
        v.y = (2047 == k)  ? 1.f : 0.f;
        v.z = (0 == k2)    ? 1.f : 0.f;
        v.w = (1 == k2)    ? 1.f : 0.f;
    }
    __stcs(reinterpret_cast<float4*>(base + 2) + i4, v);
}

// ---------------- kernel 9: scalars ----------------
__global__ void final_kernel(float* __restrict__ out) {
    __shared__ float sh[256];
    int t = threadIdx.x;
    float s = 0.f;
    for (int k = t; k < K; k += 256) {
        float p = (float)g_counts[k] * (1.0f / (float)NPIX);
        s += p * logf(p + 1e-10f);
    }
    sh[t] = s;
    __syncthreads();
    for (int o = 128; o; o >>= 1) {
        if (t < o) sh[t] += sh[t + o];
        __syncthreads();
    }
    if (t == 0) {
        out[0] = 0.25f * g_loss / (float)QELEMS;
        out[1 + QELEMS] = expf(-sh[0]);
    }
}

extern "C" void kernel_launch(void* const* d_in, const int* in_sizes, int n_in,
                              void* d_out, int out_size) {
    const float* x   = (const float*)d_in[0];
    const float* emb = (const float*)d_in[1];
    float* out  = (float*)d_out;
    float* outq = out + 1;
    float* encb = out + 2 + QELEMS;

    cudaFuncSetAttribute(argmin_fp16_kernel, cudaFuncAttributeMaxDynamicSharedMemorySize,
                         SMEM_BYTES);

    prep_kernel<<<8, 256>>>(emb);                           // 0
    split_x_kernel<<<1024, 256>>>(x);                       // 1
    split_e_kernel<<<32, 256>>>(emb);                       // 2
    argmin_fp16_kernel<<<1024, 256, SMEM_BYTES>>>();        // 3 (profiled slot)
    merge_kernel<<<NPIX / 256, 256>>>();                    // 4
    brute_kernel<<<296, 256>>>(x, emb);                     // 5
    fix_kernel<<<64, 256>>>();                              // 6
    quantize_kernel<<<NPIX / 32, 256>>>(x, emb, outq);      // 7
    enc_kernel<<<131072, 256>>>(encb);                      // 8
    final_kernel<<<1, 256>>>(out);                          // 9
}

// round 17
// speedup vs baseline: 1.9848x; 1.0529x over previous
#include <cuda_runtime.h>
#include <cuda_fp16.h>
#include <cstdint>

#define D      256
#define K      2048
#define BHW    4096
#define NPIX   65536
#define QELEMS 16777216
#define MARGIN 0.05f

// ---------------- device scratch ----------------
// A scratch (hi only): [pt 512][px 128][c 32 (^= px&7)] uint4
__device__ uint4 g_xA[(size_t)512 * 128 * 32];          // 32 MB
// B scratch (hi only): [slice 64][n 128][cl 8 (^= n&7)] uint4  (slice = kt*4+s)
__device__ uint4 g_xB[(size_t)64 * 128 * 8];            // 1 MB
__device__ float g_halfnorm[K];
__device__ int   g_idx[NPIX];
__device__ int   g_counts[K];
__device__ float g_loss;
__device__ int   g_ambig_cnt;
__device__ int   g_ambig[NPIX];
__device__ unsigned long long g_bmin[NPIX];   // packed (sortable score, idx) minima
// per-half top2 results
__device__ float g_bestv[2 * NPIX];
__device__ float g_best2[2 * NPIX];
__device__ int   g_besti[2 * NPIX];

__device__ __forceinline__ void mma16(float* c, const uint32_t* a, const uint32_t* b) {
    asm volatile("mma.sync.aligned.m16n8k16.row.col.f32.f16.f16.f32 "
        "{%0,%1,%2,%3}, {%4,%5,%6,%7}, {%8,%9}, {%0,%1,%2,%3};"
        : "+f"(c[0]), "+f"(c[1]), "+f"(c[2]), "+f"(c[3])
        : "r"(a[0]), "r"(a[1]), "r"(a[2]), "r"(a[3]), "r"(b[0]), "r"(b[1]));
}
__device__ __forceinline__ void ldsm4(uint32_t* r, uint32_t addr) {
    asm volatile("ldmatrix.sync.aligned.m8n8.x4.shared.b16 {%0,%1,%2,%3}, [%4];"
        : "=r"(r[0]), "=r"(r[1]), "=r"(r[2]), "=r"(r[3]) : "r"(addr));
}
__device__ __forceinline__ uint32_t smem_u32(const void* p) {
    uint32_t a;
    asm("{ .reg .u64 t; cvta.to.shared.u64 t, %1; cvt.u32.u64 %0, t; }" : "=r"(a) : "l"(p));
    return a;
}
#define CPASYNC(dst, src) \
    asm volatile("cp.async.ca.shared.global [%0], [%1], 16;" :: "r"(dst), "l"(src))
#define CPCOMMIT() asm volatile("cp.async.commit_group;" ::: "memory")
#define CPWAIT0()  asm volatile("cp.async.wait_group 0;" ::: "memory")

__device__ __forceinline__ uint32_t packh2(float a, float b) {
    __half2 h2 = __halves2half2(__float2half_rn(a), __float2half_rn(b));
    return *reinterpret_cast<uint32_t*>(&h2);
}
// float -> order-preserving uint32
__device__ __forceinline__ uint32_t fkey(float f) {
    uint32_t u = __float_as_uint(f);
    return u ^ (((int)u >> 31) | 0x80000000u);
}

// ---------------- kernel 1: -x -> fp16 hi, ldmatrix-ready A scratch ----------------
__global__ void split_x_kernel(const float* __restrict__ x) {
    __shared__ uint4 stg[64 * 32];   // [pxl][cs]
    int blk = blockIdx.x;
    int b = blk >> 6, pt = (blk >> 1) & 31, hpx = blk & 1;
    int tid = threadIdx.x;
    int hw0 = pt * 128 + hpx * 64;

    #pragma unroll
    for (int it = 0; it < 8; it++) {
        int id = tid + it * 256;
        int pxl = id & 63, c = id >> 6;
        float v[8];
        #pragma unroll
        for (int j = 0; j < 8; j++)
            v[j] = -x[((size_t)(b * 256 + c * 8 + j)) * 4096 + hw0 + pxl];
        uint4 hi;
        hi.x = packh2(v[0], v[1]); hi.y = packh2(v[2], v[3]);
        hi.z = packh2(v[4], v[5]); hi.w = packh2(v[6], v[7]);
        stg[pxl * 32 + (c ^ (pxl & 7))] = hi;
    }
    __syncthreads();
    size_t ob = (size_t)(blk >> 1) * 4096;
    #pragma unroll
    for (int it = 0; it < 8; it++) {
        int id = tid + it * 256;
        int pxl = id >> 5, cp = id & 31;
        g_xA[ob + (size_t)(hpx * 64 + pxl) * 32 + cp] = stg[pxl * 32 + cp];
    }
}

// ---------------- kernel 2: e -> fp16 hi B scratch + halfnorm + init (prep fused) ----------------
__global__ void split_e_kernel(const float* __restrict__ emb) {
    __shared__ uint4 stg[64 * 32];   // [nl][s*8 + swz(cl)]
    int n0 = blockIdx.x * 64;
    int tid = threadIdx.x;
    int lane = tid & 31;
    #pragma unroll
    for (int it = 0; it < 8; it++) {
        int id = tid + it * 256;
        int c = id & 31, nl = id >> 5;
        float v[8];
        #pragma unroll
        for (int j = 0; j < 8; j++)
            v[j] = emb[(size_t)(n0 + nl) * D + c * 8 + j];
        float s2 = 0.f;
        #pragma unroll
        for (int j = 0; j < 8; j++) s2 = fmaf(v[j], v[j], s2);
        #pragma unroll
        for (int off = 16; off; off >>= 1)
            s2 += __shfl_xor_sync(0xffffffffu, s2, off);
        if (lane == 0) g_halfnorm[n0 + nl] = 0.5f * s2;
        uint4 hi;
        hi.x = packh2(v[0], v[1]); hi.y = packh2(v[2], v[3]);
        hi.z = packh2(v[4], v[5]); hi.w = packh2(v[6], v[7]);
        int s = c >> 3, cl = c & 7;
        stg[nl * 32 + s * 8 + (cl ^ (nl & 7))] = hi;
    }
    if (tid < 64) g_counts[n0 + tid] = 0;
    if (blockIdx.x == 0 && tid == 0) { g_loss = 0.f; g_ambig_cnt = 0; }
    __syncthreads();
    int kt = n0 >> 7, nh = (n0 >> 6) & 1;
    #pragma unroll
    for (int it = 0; it < 8; it++) {
        int id = tid + it * 256;        // [s 4][nl 64][clp 8]
        int clp = id & 7, nl = (id >> 3) & 63, s = id >> 9;
        g_xB[((size_t)(kt * 4 + s) * 128 + nh * 64 + nl) * 8 + clp] =
            stg[nl * 32 + s * 8 + clp];
    }
}

// ---------------- kernel 3: fp16-hi screening GEMM, K-split, 2 CTA/SM ----------------
#define BOFF   65536
#define BUFSZ  16384
#define HNB    98304
#define SRVB   102400
#define SR2B   103424
#define SRIB   104448
#define SMEM_BYTES 105472

__global__ __launch_bounds__(256, 2) void argmin_fp16_kernel() {
    extern __shared__ uint4 sm4[];
    uint32_t sb = smem_u32(sm4);
    char* smc = reinterpret_cast<char*>(sm4);
    float* hnsm = reinterpret_cast<float*>(smc + HNB);
    float* srv  = reinterpret_cast<float*>(smc + SRVB);
    float* sr2  = reinterpret_cast<float*>(smc + SR2B);
    int*   sri  = reinterpret_cast<int*>(smc + SRIB);

    int tid = threadIdx.x;
    int w = tid >> 5, lane = tid & 31;
    int warpM = w >> 1, warpN = w & 1;        // 4 x 2 warps; tile 32px x 64n
    int g = lane >> 2, tig = lane & 3;
    int khalf = blockIdx.x & 1, pt = blockIdx.x >> 1;

    srv[tid] = 3.4e38f; sr2[tid] = 3.4e38f; sri[tid] = 0;

    // prologue: A resident (16/thread) + B step0 (4/thread)
    {
        const uint4* asrc = &g_xA[(size_t)pt * 4096];
        #pragma unroll
        for (int i = 0; i < 16; i++) {
            int id = tid + i * 256;
            CPASYNC(sb + id * 16, asrc + id);
        }
        const uint4* bsrc = &g_xB[(size_t)khalf * 32768];
        #pragma unroll
        for (int i = 0; i < 4; i++) {
            int id = tid + i * 256;
            CPASYNC(sb + BOFF + id * 16, bsrc + id);
        }
        CPCOMMIT();
        #pragma unroll
        for (int i = 0; i < 4; i++)
            hnsm[tid + i * 256] = g_halfnorm[khalf * 1024 + tid + i * 256];
        CPWAIT0();
    }

    int pxA0 = warpM * 32 + (lane & 15);
    int kcA  = lane >> 4;
    int nB0  = warpN * 64 + (lane & 7) + ((lane >> 4) << 3);
    int kcB  = (lane >> 3) & 1;

    float acc[2][8][4];

    for (int nt = 0; nt < 8; nt++) {
        #pragma unroll
        for (int mf = 0; mf < 2; mf++)
            #pragma unroll
            for (int nf = 0; nf < 8; nf++)
                #pragma unroll
                for (int i = 0; i < 4; i++) acc[mf][nf][i] = 0.f;

        for (int s = 0; s < 4; s++) {          // 64-d slices
            int step = nt * 4 + s;
            int buf = step & 1;
            __syncthreads();
            if (step < 31) {
                const uint4* bsrc = &g_xB[((size_t)khalf * 32 + step + 1) * 1024];
                uint32_t bdst = sb + BOFF + (buf ^ 1) * BUFSZ;
                #pragma unroll
                for (int i = 0; i < 4; i++) {
                    int id = tid + i * 256;
                    CPASYNC(bdst + id * 16, bsrc + id);
                }
                CPCOMMIT();
            }
            uint32_t bbase = sb + BOFF + buf * BUFSZ;
            #pragma unroll
            for (int kb = 0; kb < 4; kb++) {
                int cA = s * 8 + kb * 2 + kcA;
                uint32_t ah[2][4];
                #pragma unroll
                for (int mf = 0; mf < 2; mf++) {
                    int px = pxA0 + mf * 16;
                    uint32_t ro = (uint32_t)(px * 32 + (cA ^ (px & 7))) * 16;
                    ldsm4(ah[mf], sb + ro);
                }
                int clB = kb * 2 + kcB;
                uint32_t bh[4][4];
                #pragma unroll
                for (int p = 0; p < 4; p++) {
                    int n = nB0 + p * 16;
                    uint32_t ro = (uint32_t)(n * 8 + (clB ^ (n & 7))) * 16;
                    ldsm4(bh[p], bbase + ro);
                }
                #pragma unroll
                for (int mf = 0; mf < 2; mf++)
                    #pragma unroll
                    for (int nf = 0; nf < 8; nf++)
                        mma16(acc[mf][nf], ah[mf], &bh[nf >> 1][(nf & 1) * 2]);
            }
            CPWAIT0();
        }
        // epilogue: add halfnorm (from smem), per-pixel top-2 fold
        float hn[8][2];
        int clocal = nt * 128 + warpN * 64 + tig * 2;
        #pragma unroll
        for (int nf = 0; nf < 8; nf++) {
            hn[nf][0] = hnsm[clocal + nf * 8];
            hn[nf][1] = hnsm[clocal + nf * 8 + 1];
        }
        #pragma unroll
        for (int mf = 0; mf < 2; mf++) {
            #pragma unroll
            for (int half = 0; half < 2; half++) {
                float v = 3.4e38f, v2 = 3.4e38f; int vi = 0;
                #pragma unroll
                for (int nf = 0; nf < 8; nf++) {
                    #pragma unroll
                    for (int c = 0; c < 2; c++) {
                        float sc = acc[mf][nf][half * 2 + c] + hn[nf][c];
                        int ci = khalf * 1024 + clocal + nf * 8 + c;
                        if (sc < v) { v2 = v; v = sc; vi = ci; }
                        else if (sc < v2) { v2 = sc; }
                    }
                }
                #pragma unroll
                for (int o = 1; o <= 2; o <<= 1) {
                    float ov  = __shfl_xor_sync(0xffffffffu, v, o);
                    int   oi  = __shfl_xor_sync(0xffffffffu, vi, o);
                    float ov2 = __shfl_xor_sync(0xffffffffu, v2, o);
                    float nv2 = fminf(fmaxf(v, ov), fminf(v2, ov2));
                    bool take = (ov < v) || (ov == v && oi < vi);
                    if (take) { v = ov; vi = oi; }
                    v2 = nv2;
                }
                if (tig == 0) {
                    int row = warpM * 32 + mf * 16 + half * 8 + g;
                    int slot = row * 2 + warpN;
                    float sv = srv[slot], sv2 = sr2[slot]; int si = sri[slot];
                    float nv2 = fminf(fmaxf(v, sv), fminf(v2, sv2));
                    bool take = (v < sv) || (v == sv && vi < si);
                    srv[slot] = take ? v : sv;
                    sri[slot] = take ? vi : si;
                    sr2[slot] = nv2;
                }
            }
        }
    }
    __syncthreads();
    if (tid < 128) {
        float v = srv[tid * 2], v2 = sr2[tid * 2]; int vi = sri[tid * 2];
        {
            float ov = srv[tid * 2 + 1], ov2 = sr2[tid * 2 + 1];
            int oi = sri[tid * 2 + 1];
            float nv2 = fminf(fmaxf(v, ov), fminf(v2, ov2));
            bool take = (ov < v) || (ov == v && oi < vi);
            if (take) { v = ov; vi = oi; }
            v2 = nv2;
        }
        int n = pt * 128 + tid;
        g_bestv[khalf * NPIX + n] = v;
        g_best2[khalf * NPIX + n] = v2;
        g_besti[khalf * NPIX + n] = vi;
    }
}

// ---------------- kernel 4: merge halves -> idx, counts, ambig list ----------------
__global__ void merge_kernel() {
    int n = blockIdx.x * 256 + threadIdx.x;
    float v0 = g_bestv[n],        v1 = g_bestv[NPIX + n];
    float w0 = g_best2[n],        w1 = g_best2[NPIX + n];
    int   i0 = g_besti[n],        i1 = g_besti[NPIX + n];
    bool t1 = v1 < v0;
    float v  = t1 ? v1 : v0;
    int   vi = t1 ? i1 : i0;
    float v2 = fminf(t1 ? v0 : v1, t1 ? w1 : w0);
    g_idx[n] = vi;
    atomicAdd(&g_counts[vi], 1);
    if (v2 - v < MARGIN) {
        int pos = atomicAdd(&g_ambig_cnt, 1);
        g_ambig[pos] = n;
        g_bmin[n] = 0xFFFFFFFFFFFFFFFFULL;
    }
}

// ---------------- kernel 5: exact fp32 brute, (16px, 256-code) units ----------------
#define BPX 16
__global__ __launch_bounds__(256, 2) void brute_kernel(const float* __restrict__ x,
                                                       const float* __restrict__ emb) {
    __shared__ float sx[BPX][256];
    int tid = threadIdx.x;
    int lane = tid & 31;
    int seg = tid & 7, kg = (tid >> 3) & 31;
    int count = g_ambig_cnt;
    int ngroups = (count + BPX - 1) / BPX;
    int nunits = ngroups * 8;

    for (int u = blockIdx.x; u < nunits; u += gridDim.x) {
        int grp = u >> 3, kc = u & 7;
        int base = grp * BPX;
        __syncthreads();
        for (int i = tid; i < BPX * 256; i += 256) {
            int px = i >> 8, d = i & 255;
            int li = base + px;
            int n = g_ambig[li < count ? li : count - 1];
            sx[px][d] = x[(((size_t)(n >> 12) * 256 + d) << 12) | (uint32_t)(n & 4095)];
        }
        __syncthreads();
        float best[BPX]; int bik[BPX];
        #pragma unroll
        for (int p = 0; p < BPX; p++) { best[p] = 3.4e38f; bik[p] = 0; }

        for (int kt = 0; kt < 8; kt++) {
            int k = kc * 256 + kt * 32 + kg;
            const float4* er = reinterpret_cast<const float4*>(emb + (size_t)k * 256);
            float4 e[8];
            #pragma unroll
            for (int c = 0; c < 8; c++) e[c] = er[c * 8 + seg];
            float hn = g_halfnorm[k];
            #pragma unroll
            for (int p = 0; p < BPX; p++) {
                float dot = 0.f;
                #pragma unroll
                for (int c = 0; c < 8; c++) {
                    const float* xs = &sx[p][c * 32 + seg * 4];
                    dot = fmaf(xs[0], e[c].x, dot);
                    dot = fmaf(xs[1], e[c].y, dot);
                    dot = fmaf(xs[2], e[c].z, dot);
                    dot = fmaf(xs[3], e[c].w, dot);
                }
                dot += __shfl_xor_sync(0xffffffffu, dot, 1);
                dot += __shfl_xor_sync(0xffffffffu, dot, 2);
                dot += __shfl_xor_sync(0xffffffffu, dot, 4);
                float sc = hn - dot;
                if (sc < best[p]) { best[p] = sc; bik[p] = k; }
            }
        }
        #pragma unroll
        for (int p = 0; p < BPX; p++) {
            float v = best[p]; int vi = bik[p];
            #pragma unroll
            for (int o = 8; o <= 16; o <<= 1) {
                float ov = __shfl_xor_sync(0xffffffffu, v, o);
                int   oi = __shfl_xor_sync(0xffffffffu, vi, o);
                if (ov < v || (ov == v && oi < vi)) { v = ov; vi = oi; }
            }
            if (lane == 0) {
                int li = base + p;
                if (li < count) {
                    unsigned long long key =
                        ((unsigned long long)fkey(v) << 32) | (unsigned)vi;
                    atomicMin(&g_bmin[g_ambig[li]], key);
                }
            }
        }
    }
}

// ---------------- kernel 6: apply brute results ----------------
__global__ void fix_kernel() {
    int count = g_ambig_cnt;
    for (int i = blockIdx.x * 256 + threadIdx.x; i < count; i += gridDim.x * 256) {
        int n = g_ambig[i];
        int vi = (int)(g_bmin[n] & 0xFFFFFFFFu);
        int old = g_idx[n];
        if (old != vi) {
            g_idx[n] = vi;
            atomicAdd(&g_counts[old], -1);
            atomicAdd(&g_counts[vi], 1);
        }
    }
}

// ---------------- kernel 7: gather + loss (float4 loads, scalar stores) ----------------
// outq = out + 1 is only 4B-aligned -> stores must be scalar.
__global__ __launch_bounds__(256) void quantize_kernel(const float* __restrict__ x,
                                                       const float* __restrict__ emb,
                                                       float* __restrict__ outq) {
    __shared__ float sq[32 * 257];
    __shared__ int   sk[32];
    __shared__ float ls[8];
    int tid = threadIdx.x;
    int n0 = blockIdx.x * 32;
    int b = n0 >> 12, hw0 = n0 & 4095;
    if (tid < 32) sk[tid] = g_idx[n0 + tid];
    __syncthreads();
    #pragma unroll 8
    for (int j = 0; j < 32; j++) {
        sq[j * 257 + tid] = __ldg(emb + (size_t)sk[j] * 256 + tid);
    }
    __syncthreads();
    float l = 0.f;
    int px = (tid & 7) * 4, dr = tid >> 3;     // 4 consecutive px, 32 d-rows/iter
    #pragma unroll
    for (int j = 0; j < 8; j++) {
        int d = j * 32 + dr;
        size_t o = ((size_t)(b * 256 + d)) * 4096 + hw0 + px;
        float4 xv = *reinterpret_cast<const float4*>(x + o);
        float q0 = sq[(px + 0) * 257 + d];
        float q1 = sq[(px + 1) * 257 + d];
        float q2 = sq[(px + 2) * 257 + d];
        float q3 = sq[(px + 3) * 257 + d];
        __stcs(outq + o + 0, q0);
        __stcs(outq + o + 1, q1);
        __stcs(outq + o + 2, q2);
        __stcs(outq + o + 3, q3);
        float d0 = q0 - xv.x, d1 = q1 - xv.y, d2 = q2 - xv.z, d3 = q3 - xv.w;
        l = fmaf(d0, d0, l); l = fmaf(d1, d1, l);
        l = fmaf(d2, d2, l); l = fmaf(d3, d3, l);
    }
    #pragma unroll
    for (int off = 16; off; off >>= 1) l += __shfl_xor_sync(0xffffffffu, l, off);
    int lane = tid & 31, wq = tid >> 5;
    if (lane == 0) ls[wq] = l;
    __syncthreads();
    if (tid == 0) {
        float ssum = 0.f;
        #pragma unroll
        for (int i = 0; i < 8; i++) ssum += ls[i];
        atomicAdd(&g_loss, ssum);
    }
}

// ---------------- kernel 8: one-hot encodings, float4 stores ----------------
__global__ void enc_kernel(float* __restrict__ base) {
    size_t i4 = (size_t)blockIdx.x * 256 + threadIdx.x;
    const size_t LAST = ((size_t)NPIX * K - 2) / 4;
    if (i4 == 0) {
        int k = g_idx[0];
        __stcs(base + 0, (0 == k) ? 1.f : 0.f);
        __stcs(base + 1, (1 == k) ? 1.f : 0.f);
    }
    if (i4 >= LAST) {
        if (i4 == LAST) {
            int k = g_idx[NPIX - 1];
            __stcs(base + (size_t)NPIX * K - 2, (K - 2 == k) ? 1.f : 0.f);
            __stcs(base + (size_t)NPIX * K - 1, (K - 1 == k) ? 1.f : 0.f);
        }
        return;
    }
    size_t e0 = i4 * 4 + 2;
    int n = (int)(e0 >> 11), j = (int)(e0 & 2047);
    int k = g_idx[n];
    float4 v;
    if (j != 2046) {
        v.x = (j     == k) ? 1.f : 0.f;
        v.y = (j + 1 == k) ? 1.f : 0.f;
        v.z = (j + 2 == k) ? 1.f : 0.f;
        v.w = (j + 3 == k) ? 1.f : 0.f;
    } else {
        int k2 = g_idx[n + 1];
        v.x = (2046 == k)  ? 1.f : 0.f;
        v.y = (2047 == k)  ? 1.f : 0.f;
        v.z = (0 == k2)    ? 1.f : 0.f;
        v.w = (1 == k2)    ? 1.f : 0.f;
    }
    __stcs(reinterpret_cast<float4*>(base + 2) + i4, v);
}

// ---------------- kernel 9: scalars ----------------
__global__ void final_kernel(float* __restrict__ out) {
    __shared__ float sh[256];
    int t = threadIdx.x;
    float s = 0.f;
    for (int k = t; k < K; k += 256) {
        float p = (float)g_counts[k] * (1.0f / (float)NPIX);
        s += p * logf(p + 1e-10f);
    }
    sh[t] = s;
    __syncthreads();
    for (int o = 128; o; o >>= 1) {
        if (t < o) sh[t] += sh[t + o];
        __syncthreads();
    }
    if (t == 0) {
        out[0] = 0.25f * g_loss / (float)QELEMS;
        out[1 + QELEMS] = expf(-sh[0]);
    }
}

extern "C" void kernel_launch(void* const* d_in, const int* in_sizes, int n_in,
                              void* d_out, int out_size) {
    const float* x   = (const float*)d_in[0];
    const float* emb = (const float*)d_in[1];
    float* out  = (float*)d_out;
    float* outq = out + 1;
    float* encb = out + 2 + QELEMS;

    cudaFuncSetAttribute(argmin_fp16_kernel, cudaFuncAttributeMaxDynamicSharedMemorySize,
                         SMEM_BYTES);

    split_x_kernel<<<1024, 256>>>(x);                       // 0
    split_e_kernel<<<32, 256>>>(emb);                       // 1 (prep fused)
    argmin_fp16_kernel<<<1024, 256, SMEM_BYTES>>>();        // 2
    merge_kernel<<<NPIX / 256, 256>>>();                    // 3
    brute_kernel<<<296, 256>>>(x, emb);                     // 4
    fix_kernel<<<64, 256>>>();                              // 5
    quantize_kernel<<<NPIX / 32, 256>>>(x, emb, outq);      // 6
    enc_kernel<<<131072, 256>>>(encb);                      // 7
    final_kernel<<<1, 256>>>(out);                          // 8
}